// round 12
// baseline (speedup 1.0000x reference)
#include <cuda_runtime.h>
#include <cuda_bf16.h>
#include <math.h>
#include <stdint.h>

#define NN 50000
#define EE 800000
#define FF 256
#define NTILES 391  // ceil(50000/128)

// ---------------- device scratch (no runtime allocation allowed) ------------
__device__ int   g_is64;
__device__ int   g_cnt[NN];
__device__ int   g_cursor[NN];
__device__ int   g_rowstart[NN + 1];
__device__ float g_dis[NN];
__device__ int   g_esrc[EE];
__device__ float g_enorm[EE];
__device__ float g_T [(size_t)NN * FF];
__device__ float g_HA[(size_t)NN * FF];
__device__ float g_HB[(size_t)NN * FF];
__device__ float g_t2[NN * 2];
__device__ __nv_bfloat16 g_Whi[3][FF * FF];  // W^T split-high, [n][k]
__device__ __nv_bfloat16 g_Wlo[3][FF * FF];  // W^T split-low,  [n][k]

// ---------------- small helpers ---------------------------------------------
__device__ __forceinline__ int load_edge(const void* ei, long long idx) {
    if (g_is64) return (int)((const long long*)ei)[idx];
    return ((const int*)ei)[idx];
}

// init counters + int64/int32 detection in one launch
__global__ void k_detect_init(const int* p) {
    int i = blockIdx.x * blockDim.x + threadIdx.x;
    if (i < NN) { g_cnt[i] = 0; g_cursor[i] = 0; }
    if (blockIdx.x == 0 && threadIdx.x == 0) {
        int any = 0;
        #pragma unroll
        for (int j = 1; j < 64; j += 2) any |= p[j];
        g_is64 = (any == 0) ? 1 : 0;
    }
}

__global__ void k_count(const void* ei) {
    int e = blockIdx.x * blockDim.x + threadIdx.x;
    if (e >= EE) return;
    int dst = load_edge(ei, (long long)EE + e);
    atomicAdd(&g_cnt[dst], 1);
}

// Exclusive scan of g_cnt -> g_rowstart, fused with g_dis computation.
#define SCAN_PER 49
__global__ void k_scan() {
    __shared__ int warptot[32];
    int tid  = threadIdx.x;
    int lane = tid & 31;
    int wid  = tid >> 5;
    int base = tid * SCAN_PER;
    int sum = 0;
    #pragma unroll 7
    for (int i = 0; i < SCAN_PER; i++) {
        int idx = base + i;
        sum += (idx < NN) ? g_cnt[idx] : 0;
    }
    int x = sum;
    #pragma unroll
    for (int off = 1; off < 32; off <<= 1) {
        int n = __shfl_up_sync(0xffffffffu, x, off);
        if (lane >= off) x += n;
    }
    if (lane == 31) warptot[wid] = x;
    __syncthreads();
    if (wid == 0) {
        int w = warptot[lane];
        #pragma unroll
        for (int off = 1; off < 32; off <<= 1) {
            int n = __shfl_up_sync(0xffffffffu, w, off);
            if (lane >= off) w += n;
        }
        warptot[lane] = w;
    }
    __syncthreads();
    int offset = x - sum;
    if (wid > 0) offset += warptot[wid - 1];
    int running = offset;
    #pragma unroll 7
    for (int i = 0; i < SCAN_PER; i++) {
        int idx = base + i;
        if (idx < NN) {
            int c = g_cnt[idx];
            g_rowstart[idx] = running;
            g_dis[idx] = rsqrtf((float)(c + 1));  // +1 self-loop
            running += c;
        } else if (idx == NN) {
            g_rowstart[idx] = running;
        }
    }
}

__global__ void k_build(const void* ei) {
    int e = blockIdx.x * blockDim.x + threadIdx.x;
    if (e >= EE) return;
    int src = load_edge(ei, e);
    int dst = load_edge(ei, (long long)EE + e);
    float w = g_dis[src] * g_dis[dst];
    int pos = g_rowstart[dst] + atomicAdd(&g_cursor[dst], 1);
    g_esrc[pos]  = src;
    g_enorm[pos] = w;
}

// --------- weight split/transpose: Whi[n][k]+Wlo[n][k] = W[k][n] ------------
__global__ void k_wsplit(const float* __restrict__ W,
                         __nv_bfloat16* __restrict__ bhi,
                         __nv_bfloat16* __restrict__ blo) {
    int i = blockIdx.x * 256 + threadIdx.x;  // i = k*256 + n
    int k = i >> 8, n = i & 255;
    float w = W[i];
    __nv_bfloat16 h = __float2bfloat16_rn(w);
    __nv_bfloat16 l = __float2bfloat16_rn(w - __bfloat162float(h));
    bhi[n * 256 + k] = h;
    blo[n * 256 + k] = l;
}

// ---------------- mma.sync GEMM (sm_80 path; works on plain sm_103) ---------
// C[N,256] = (relu?)A[N,256] @ W[256,256], split-bf16 x3 passes, fp32 accum.
// Block 128(M)x128(N), 8 warps (2M x 4N), warp tile 64x32, K chunk 64.
#define AST 72    // A smem row stride (bf16): 36 words, mod32=4 -> conflict-free
#define WST 264   // W smem row stride (bf16): 132 words, mod32=4 -> conflict-free
#define SM_W  (128 * WST * 2)          // 67584 B per half (hi or lo)
#define SM_A  (128 * AST * 2)          // 18432 B per half
#define SM_TOT (2 * SM_W + 2 * SM_A)   // 172032 B

__device__ __forceinline__ void mma_bf16(float c[4], const uint32_t a[4],
                                         const uint32_t b[2]) {
    asm volatile(
        "mma.sync.aligned.m16n8k16.row.col.f32.bf16.bf16.f32 "
        "{%0,%1,%2,%3}, {%4,%5,%6,%7}, {%8,%9}, {%0,%1,%2,%3};"
        : "+f"(c[0]), "+f"(c[1]), "+f"(c[2]), "+f"(c[3])
        : "r"(a[0]), "r"(a[1]), "r"(a[2]), "r"(a[3]), "r"(b[0]), "r"(b[1]));
}

template <bool RELU>
__global__ __launch_bounds__(256, 1)
void k_gemm_mma(const float* __restrict__ A,
                const __nv_bfloat16* __restrict__ WThi,
                const __nv_bfloat16* __restrict__ WTlo,
                float* __restrict__ C) {
    extern __shared__ __align__(16) char smem[];
    __nv_bfloat16* sWhi = (__nv_bfloat16*)smem;
    __nv_bfloat16* sWlo = sWhi + 128 * WST;
    __nv_bfloat16* sAhi = sWlo + 128 * WST;
    __nv_bfloat16* sAlo = sAhi + 128 * AST;

    const int tid  = threadIdx.x;
    const int wid  = tid >> 5;
    const int lane = tid & 31;
    const int g    = lane >> 2;   // group id (row/col within fragment)
    const int cc   = lane & 3;    // thread-in-group
    const int warpM = wid & 1;
    const int warpN = wid >> 1;
    const int rowBase = blockIdx.x * 128;
    const int nGlob   = blockIdx.y * 128;

    // ---- stage W^T half (128 n-rows x 256 k), hi+lo, once per block ----
    {
        const __nv_bfloat16* srcH = WThi + (size_t)nGlob * 256;
        const __nv_bfloat16* srcL = WTlo + (size_t)nGlob * 256;
        #pragma unroll
        for (int it = 0; it < 16; it++) {
            int idx = tid + it * 256;          // 128*32 16B-chunks
            int n  = idx >> 5;
            int kq = idx & 31;                 // 8-bf16 chunk
            *(uint4*)(sWhi + n * WST + kq * 8) =
                *(const uint4*)(srcH + n * 256 + kq * 8);
            *(uint4*)(sWlo + n * WST + kq * 8) =
                *(const uint4*)(srcL + n * 256 + kq * 8);
        }
    }

    float acc[4][4][4];
    #pragma unroll
    for (int i = 0; i < 4; i++)
        #pragma unroll
        for (int j = 0; j < 4; j++)
            #pragma unroll
            for (int q = 0; q < 4; q++) acc[i][j][q] = 0.f;

    const int rS = tid >> 1;    // staging row 0..127
    const int hS = tid & 1;     // staging k-half (32 fp32)
    const bool vS = (rowBase + rS) < NN;

    for (int kc = 0; kc < 4; kc++) {
        __syncthreads();  // W staged (it=0) / previous chunk consumed
        // ---- stage A chunk: 128 rows x 64 k, fp32 -> split bf16, relu ----
        {
            const float* src = A + (size_t)(rowBase + rS) * 256 + kc * 64 + hS * 32;
            __nv_bfloat16* dH = sAhi + rS * AST + hS * 32;
            __nv_bfloat16* dL = sAlo + rS * AST + hS * 32;
            #pragma unroll
            for (int q = 0; q < 4; q++) {   // 8 fp32 per iter
                float4 f0 = vS ? *(const float4*)(src + q * 8)
                               : make_float4(0.f, 0.f, 0.f, 0.f);
                float4 f1 = vS ? *(const float4*)(src + q * 8 + 4)
                               : make_float4(0.f, 0.f, 0.f, 0.f);
                if (RELU) {
                    f0.x = fmaxf(f0.x, 0.f); f0.y = fmaxf(f0.y, 0.f);
                    f0.z = fmaxf(f0.z, 0.f); f0.w = fmaxf(f0.w, 0.f);
                    f1.x = fmaxf(f1.x, 0.f); f1.y = fmaxf(f1.y, 0.f);
                    f1.z = fmaxf(f1.z, 0.f); f1.w = fmaxf(f1.w, 0.f);
                }
                __nv_bfloat162 h0 = __float22bfloat162_rn(make_float2(f0.x, f0.y));
                __nv_bfloat162 h1 = __float22bfloat162_rn(make_float2(f0.z, f0.w));
                __nv_bfloat162 h2 = __float22bfloat162_rn(make_float2(f1.x, f1.y));
                __nv_bfloat162 h3 = __float22bfloat162_rn(make_float2(f1.z, f1.w));
                __nv_bfloat162 l0 = __float22bfloat162_rn(make_float2(
                    f0.x - __bfloat162float(h0.x), f0.y - __bfloat162float(h0.y)));
                __nv_bfloat162 l1 = __float22bfloat162_rn(make_float2(
                    f0.z - __bfloat162float(h1.x), f0.w - __bfloat162float(h1.y)));
                __nv_bfloat162 l2 = __float22bfloat162_rn(make_float2(
                    f1.x - __bfloat162float(h2.x), f1.y - __bfloat162float(h2.y)));
                __nv_bfloat162 l3 = __float22bfloat162_rn(make_float2(
                    f1.z - __bfloat162float(h3.x), f1.w - __bfloat162float(h3.y)));
                ((__nv_bfloat162*)(dH + q * 8))[0] = h0;
                ((__nv_bfloat162*)(dH + q * 8))[1] = h1;
                ((__nv_bfloat162*)(dH + q * 8))[2] = h2;
                ((__nv_bfloat162*)(dH + q * 8))[3] = h3;
                ((__nv_bfloat162*)(dL + q * 8))[0] = l0;
                ((__nv_bfloat162*)(dL + q * 8))[1] = l1;
                ((__nv_bfloat162*)(dL + q * 8))[2] = l2;
                ((__nv_bfloat162*)(dL + q * 8))[3] = l3;
            }
        }
        __syncthreads();

        #pragma unroll
        for (int ks = 0; ks < 4; ks++) {
            const int ka = ks * 16 + 2 * cc;            // within A chunk
            const int kw = kc * 64 + ks * 16 + 2 * cc;  // within full W row
            uint32_t ah[4][4], al[4][4], bh[4][2], bl[4][2];
            #pragma unroll
            for (int i = 0; i < 4; i++) {
                const __nv_bfloat16* p =
                    sAhi + (warpM * 64 + i * 16 + g) * AST + ka;
                ah[i][0] = *(const uint32_t*)p;
                ah[i][1] = *(const uint32_t*)(p + 8 * AST);
                ah[i][2] = *(const uint32_t*)(p + 8);
                ah[i][3] = *(const uint32_t*)(p + 8 * AST + 8);
                const __nv_bfloat16* q =
                    sAlo + (warpM * 64 + i * 16 + g) * AST + ka;
                al[i][0] = *(const uint32_t*)q;
                al[i][1] = *(const uint32_t*)(q + 8 * AST);
                al[i][2] = *(const uint32_t*)(q + 8);
                al[i][3] = *(const uint32_t*)(q + 8 * AST + 8);
            }
            #pragma unroll
            for (int j = 0; j < 4; j++) {
                const __nv_bfloat16* p =
                    sWhi + (warpN * 32 + j * 8 + g) * WST + kw;
                bh[j][0] = *(const uint32_t*)p;
                bh[j][1] = *(const uint32_t*)(p + 8);
                const __nv_bfloat16* q =
                    sWlo + (warpN * 32 + j * 8 + g) * WST + kw;
                bl[j][0] = *(const uint32_t*)q;
                bl[j][1] = *(const uint32_t*)(q + 8);
            }
            #pragma unroll
            for (int i = 0; i < 4; i++)
                #pragma unroll
                for (int j = 0; j < 4; j++) {
                    mma_bf16(acc[i][j], ah[i], bh[j]);
                    mma_bf16(acc[i][j], al[i], bh[j]);
                    mma_bf16(acc[i][j], ah[i], bl[j]);
                }
        }
    }

    // ---- epilogue: fragment -> gmem (fp32) ----
    #pragma unroll
    for (int i = 0; i < 4; i++) {
        int row0 = rowBase + warpM * 64 + i * 16 + g;
        int row1 = row0 + 8;
        #pragma unroll
        for (int j = 0; j < 4; j++) {
            int col = nGlob + warpN * 32 + j * 8 + 2 * cc;
            if (row0 < NN)
                *(float2*)(C + (size_t)row0 * 256 + col) =
                    make_float2(acc[i][j][0], acc[i][j][1]);
            if (row1 < NN)
                *(float2*)(C + (size_t)row1 * 256 + col) =
                    make_float2(acc[i][j][2], acc[i][j][3]);
        }
    }
}

// ---------------- aggregation, F=256: warp/node, CSR, 4-edge pipelined ------
__global__ void k_agg(const float4* __restrict__ T4,
                      const float*  __restrict__ bias,
                      float4* __restrict__ O4) {
    int warp = (blockIdx.x * blockDim.x + threadIdx.x) >> 5;
    int lane = threadIdx.x & 31;
    if (warp >= NN) return;
    int node = warp;
    float ws = g_dis[node];
    ws *= ws;  // self-loop weight dis^2 = 1/deg
    float4 a0 = T4[(size_t)node * 64 + lane];
    float4 a1 = T4[(size_t)node * 64 + lane + 32];
    float4 acc0 = make_float4(a0.x * ws, a0.y * ws, a0.z * ws, a0.w * ws);
    float4 acc1 = make_float4(a1.x * ws, a1.y * ws, a1.z * ws, a1.w * ws);
    int p0 = g_rowstart[node];
    int p1 = g_rowstart[node + 1];
    int p  = p0;

    // 4-edge unrolled: 4 index/weight loads, then 8 independent LDG.128s
    for (; p + 4 <= p1; p += 4) {
        int   s0 = g_esrc[p],     s1 = g_esrc[p + 1];
        int   s2 = g_esrc[p + 2], s3 = g_esrc[p + 3];
        float w0 = g_enorm[p],     w1 = g_enorm[p + 1];
        float w2 = g_enorm[p + 2], w3 = g_enorm[p + 3];
        float4 u0 = T4[(size_t)s0 * 64 + lane];
        float4 v0 = T4[(size_t)s0 * 64 + lane + 32];
        float4 u1 = T4[(size_t)s1 * 64 + lane];
        float4 v1 = T4[(size_t)s1 * 64 + lane + 32];
        float4 u2 = T4[(size_t)s2 * 64 + lane];
        float4 v2 = T4[(size_t)s2 * 64 + lane + 32];
        float4 u3 = T4[(size_t)s3 * 64 + lane];
        float4 v3 = T4[(size_t)s3 * 64 + lane + 32];
        acc0.x = fmaf(u0.x, w0, acc0.x); acc0.y = fmaf(u0.y, w0, acc0.y);
        acc0.z = fmaf(u0.z, w0, acc0.z); acc0.w = fmaf(u0.w, w0, acc0.w);
        acc1.x = fmaf(v0.x, w0, acc1.x); acc1.y = fmaf(v0.y, w0, acc1.y);
        acc1.z = fmaf(v0.z, w0, acc1.z); acc1.w = fmaf(v0.w, w0, acc1.w);
        acc0.x = fmaf(u1.x, w1, acc0.x); acc0.y = fmaf(u1.y, w1, acc0.y);
        acc0.z = fmaf(u1.z, w1, acc0.z); acc0.w = fmaf(u1.w, w1, acc0.w);
        acc1.x = fmaf(v1.x, w1, acc1.x); acc1.y = fmaf(v1.y, w1, acc1.y);
        acc1.z = fmaf(v1.z, w1, acc1.z); acc1.w = fmaf(v1.w, w1, acc1.w);
        acc0.x = fmaf(u2.x, w2, acc0.x); acc0.y = fmaf(u2.y, w2, acc0.y);
        acc0.z = fmaf(u2.z, w2, acc0.z); acc0.w = fmaf(u2.w, w2, acc0.w);
        acc1.x = fmaf(v2.x, w2, acc1.x); acc1.y = fmaf(v2.y, w2, acc1.y);
        acc1.z = fmaf(v2.z, w2, acc1.z); acc1.w = fmaf(v2.w, w2, acc1.w);
        acc0.x = fmaf(u3.x, w3, acc0.x); acc0.y = fmaf(u3.y, w3, acc0.y);
        acc0.z = fmaf(u3.z, w3, acc0.z); acc0.w = fmaf(u3.w, w3, acc0.w);
        acc1.x = fmaf(v3.x, w3, acc1.x); acc1.y = fmaf(v3.y, w3, acc1.y);
        acc1.z = fmaf(v3.z, w3, acc1.z); acc1.w = fmaf(v3.w, w3, acc1.w);
    }
    for (; p < p1; p++) {
        int   s = g_esrc[p];
        float w = g_enorm[p];
        float4 u = T4[(size_t)s * 64 + lane];
        float4 v = T4[(size_t)s * 64 + lane + 32];
        acc0.x = fmaf(u.x, w, acc0.x); acc0.y = fmaf(u.y, w, acc0.y);
        acc0.z = fmaf(u.z, w, acc0.z); acc0.w = fmaf(u.w, w, acc0.w);
        acc1.x = fmaf(v.x, w, acc1.x); acc1.y = fmaf(v.y, w, acc1.y);
        acc1.z = fmaf(v.z, w, acc1.z); acc1.w = fmaf(v.w, w, acc1.w);
    }

    float4 b0 = ((const float4*)bias)[lane];
    float4 b1 = ((const float4*)bias)[lane + 32];
    acc0.x += b0.x; acc0.y += b0.y; acc0.z += b0.z; acc0.w += b0.w;
    acc1.x += b1.x; acc1.y += b1.y; acc1.z += b1.z; acc1.w += b1.w;
    O4[(size_t)node * 64 + lane]      = acc0;
    O4[(size_t)node * 64 + lane + 32] = acc1;
}

// ---------------- last layer: t2[N,2] = relu(A) @ W3[256,2] ------------------
__global__ void k_gemm2(const float* __restrict__ A,
                        const float* __restrict__ W3,
                        float* __restrict__ t2) {
    int warp = (blockIdx.x * blockDim.x + threadIdx.x) >> 5;
    int lane = threadIdx.x & 31;
    if (warp >= NN) return;
    const float* row = A + (size_t)warp * 256;
    float s0 = 0.f, s1 = 0.f;
    #pragma unroll
    for (int k = lane; k < 256; k += 32) {
        float h = fmaxf(row[k], 0.f);
        float2 w = ((const float2*)W3)[k];
        s0 = fmaf(h, w.x, s0);
        s1 = fmaf(h, w.y, s1);
    }
    #pragma unroll
    for (int off = 16; off; off >>= 1) {
        s0 += __shfl_xor_sync(0xffffffffu, s0, off);
        s1 += __shfl_xor_sync(0xffffffffu, s1, off);
    }
    if (lane == 0) { t2[warp * 2] = s0; t2[warp * 2 + 1] = s1; }
}

// ---------------- final aggregation (F=2) into d_out -------------------------
__global__ void k_agg2(const float* __restrict__ t2,
                       const float* __restrict__ b3,
                       float* __restrict__ out) {
    int warp = (blockIdx.x * blockDim.x + threadIdx.x) >> 5;
    int lane = threadIdx.x & 31;
    if (warp >= NN) return;
    int node = warp;
    int p0 = g_rowstart[node];
    int p1 = g_rowstart[node + 1];
    float s0 = 0.f, s1 = 0.f;
    for (int p = p0 + lane; p < p1; p += 32) {
        int   s = g_esrc[p];
        float w = g_enorm[p];
        s0 = fmaf(t2[s * 2],     w, s0);
        s1 = fmaf(t2[s * 2 + 1], w, s1);
    }
    #pragma unroll
    for (int off = 16; off; off >>= 1) {
        s0 += __shfl_xor_sync(0xffffffffu, s0, off);
        s1 += __shfl_xor_sync(0xffffffffu, s1, off);
    }
    if (lane == 0) {
        float ws = g_dis[node];
        ws *= ws;
        out[node * 2]     = s0 + t2[node * 2]     * ws + b3[0];
        out[node * 2 + 1] = s1 + t2[node * 2 + 1] * ws + b3[1];
    }
}

// ---------------- launch ------------------------------------------------------
extern "C" void kernel_launch(void* const* d_in, const int* in_sizes, int n_in,
                              void* d_out, int out_size) {
    const float* x  = (const float*)d_in[0];
    const void*  ei = d_in[1];
    const float* W0 = (const float*)d_in[2];
    const float* b0 = (const float*)d_in[3];
    const float* W1 = (const float*)d_in[4];
    const float* b1 = (const float*)d_in[5];
    const float* W2 = (const float*)d_in[6];
    const float* b2 = (const float*)d_in[7];
    const float* W3 = (const float*)d_in[8];
    const float* b3 = (const float*)d_in[9];
    float* out = (float*)d_out;

    float *T, *HA, *HB, *t2;
    __nv_bfloat16 *Whi, *Wlo;
    cudaGetSymbolAddress((void**)&T,   g_T);
    cudaGetSymbolAddress((void**)&HA,  g_HA);
    cudaGetSymbolAddress((void**)&HB,  g_HB);
    cudaGetSymbolAddress((void**)&t2,  g_t2);
    cudaGetSymbolAddress((void**)&Whi, g_Whi);
    cudaGetSymbolAddress((void**)&Wlo, g_Wlo);

    static int smem_set = 0;
    if (!smem_set) {
        cudaFuncSetAttribute(k_gemm_mma<false>,
                             cudaFuncAttributeMaxDynamicSharedMemorySize, SM_TOT);
        cudaFuncSetAttribute(k_gemm_mma<true>,
                             cudaFuncAttributeMaxDynamicSharedMemorySize, SM_TOT);
        smem_set = 1;
    }

    const int nodeBlocks = (NN + 255) / 256;
    const int edgeBlocks = (EE + 255) / 256;
    const int warpBlocks = (NN + 7) / 8;
    dim3 gemmGrid(NTILES, 2);

    // ---- graph preprocessing (4 launches) ----
    k_detect_init<<<nodeBlocks, 256>>>((const int*)ei);
    k_count<<<edgeBlocks, 256>>>(ei);
    k_scan<<<1, 1024>>>();   // also computes g_dis
    k_build<<<edgeBlocks, 256>>>(ei);

    // ---- weight split/transpose ----
    k_wsplit<<<256, 256>>>(W0, Whi + 0 * FF * FF, Wlo + 0 * FF * FF);
    k_wsplit<<<256, 256>>>(W1, Whi + 1 * FF * FF, Wlo + 1 * FF * FF);
    k_wsplit<<<256, 256>>>(W2, Whi + 2 * FF * FF, Wlo + 2 * FF * FF);

    // ---- layer 1 ----
    k_gemm_mma<false><<<gemmGrid, 256, SM_TOT>>>(x, Whi, Wlo, T);
    k_agg<<<warpBlocks, 256>>>((const float4*)T, b0, (float4*)HA);
    // ---- layer 2 ----
    k_gemm_mma<true><<<gemmGrid, 256, SM_TOT>>>(HA, Whi + FF * FF, Wlo + FF * FF, T);
    k_agg<<<warpBlocks, 256>>>((const float4*)T, b1, (float4*)HB);
    // ---- layer 3 ----
    k_gemm_mma<true><<<gemmGrid, 256, SM_TOT>>>(HB, Whi + 2 * FF * FF, Wlo + 2 * FF * FF, T);
    k_agg<<<warpBlocks, 256>>>((const float4*)T, b2, (float4*)HA);
    // ---- layer 4 ----
    k_gemm2<<<warpBlocks, 256>>>(HA, W3, t2);
    k_agg2<<<warpBlocks, 256>>>(t2, b3, out);
}

// round 13
// speedup vs baseline: 1.1020x; 1.1020x over previous
#include <cuda_runtime.h>
#include <cuda_bf16.h>
#include <math.h>
#include <stdint.h>

#define NN 50000
#define EE 800000
#define FF 256
#define NTILES 391  // ceil(50000/128)

// ---------------- device scratch (no runtime allocation allowed) ------------
__device__ int   g_is64;
__device__ int   g_cnt[NN];
__device__ int   g_cursor[NN];
__device__ int   g_rowstart[NN + 1];
__device__ float g_dis[NN];
__device__ int   g_esrc[EE];
__device__ float g_enorm[EE];
__device__ float g_T [(size_t)NN * FF];
__device__ float g_HA[(size_t)NN * FF];
__device__ float g_HB[(size_t)NN * FF];
__device__ float g_t2[NN * 2];
__device__ __nv_bfloat16 g_Whi[3][FF * FF];  // W^T split-high, [n][k]
__device__ __nv_bfloat16 g_Wlo[3][FF * FF];  // W^T split-low,  [n][k]

// ---------------- small helpers ---------------------------------------------
__device__ __forceinline__ int load_edge(const void* ei, long long idx) {
    if (g_is64) return (int)((const long long*)ei)[idx];
    return ((const int*)ei)[idx];
}

// init counters + int64/int32 detection in one launch
__global__ void k_detect_init(const int* p) {
    int i = blockIdx.x * blockDim.x + threadIdx.x;
    if (i < NN) { g_cnt[i] = 0; g_cursor[i] = 0; }
    if (blockIdx.x == 0 && threadIdx.x == 0) {
        int any = 0;
        #pragma unroll
        for (int j = 1; j < 64; j += 2) any |= p[j];
        g_is64 = (any == 0) ? 1 : 0;
    }
}

__global__ void k_count(const void* ei) {
    int e = blockIdx.x * blockDim.x + threadIdx.x;
    if (e >= EE) return;
    int dst = load_edge(ei, (long long)EE + e);
    atomicAdd(&g_cnt[dst], 1);
}

// Exclusive scan of g_cnt -> g_rowstart, fused with g_dis computation.
#define SCAN_PER 49
__global__ void k_scan() {
    __shared__ int warptot[32];
    int tid  = threadIdx.x;
    int lane = tid & 31;
    int wid  = tid >> 5;
    int base = tid * SCAN_PER;
    int sum = 0;
    #pragma unroll 7
    for (int i = 0; i < SCAN_PER; i++) {
        int idx = base + i;
        sum += (idx < NN) ? g_cnt[idx] : 0;
    }
    int x = sum;
    #pragma unroll
    for (int off = 1; off < 32; off <<= 1) {
        int n = __shfl_up_sync(0xffffffffu, x, off);
        if (lane >= off) x += n;
    }
    if (lane == 31) warptot[wid] = x;
    __syncthreads();
    if (wid == 0) {
        int w = warptot[lane];
        #pragma unroll
        for (int off = 1; off < 32; off <<= 1) {
            int n = __shfl_up_sync(0xffffffffu, w, off);
            if (lane >= off) w += n;
        }
        warptot[lane] = w;
    }
    __syncthreads();
    int offset = x - sum;
    if (wid > 0) offset += warptot[wid - 1];
    int running = offset;
    #pragma unroll 7
    for (int i = 0; i < SCAN_PER; i++) {
        int idx = base + i;
        if (idx < NN) {
            int c = g_cnt[idx];
            g_rowstart[idx] = running;
            g_dis[idx] = rsqrtf((float)(c + 1));  // +1 self-loop
            running += c;
        } else if (idx == NN) {
            g_rowstart[idx] = running;
        }
    }
}

__global__ void k_build(const void* ei) {
    int e = blockIdx.x * blockDim.x + threadIdx.x;
    if (e >= EE) return;
    int src = load_edge(ei, e);
    int dst = load_edge(ei, (long long)EE + e);
    float w = g_dis[src] * g_dis[dst];
    int pos = g_rowstart[dst] + atomicAdd(&g_cursor[dst], 1);
    g_esrc[pos]  = src;
    g_enorm[pos] = w;
}

// --------- weight split/transpose for all 3 layers in ONE launch -------------
__global__ void k_wsplit3(const float* __restrict__ W0,
                          const float* __restrict__ W1,
                          const float* __restrict__ W2,
                          __nv_bfloat16* __restrict__ bhi,
                          __nv_bfloat16* __restrict__ blo) {
    int layer = blockIdx.x >> 8;                 // 256 blocks per layer
    const float* W = (layer == 0) ? W0 : (layer == 1) ? W1 : W2;
    int i = (blockIdx.x & 255) * 256 + threadIdx.x;  // i = k*256 + n
    int k = i >> 8, n = i & 255;
    float w = W[i];
    __nv_bfloat16 h = __float2bfloat16_rn(w);
    __nv_bfloat16 l = __float2bfloat16_rn(w - __bfloat162float(h));
    bhi[(size_t)layer * FF * FF + n * 256 + k] = h;
    blo[(size_t)layer * FF * FF + n * 256 + k] = l;
}

// ---------------- mma.sync GEMM (sm_80 path; works on plain sm_103) ---------
// C[N,256] = (relu?)A[N,256] @ W[256,256], split-bf16 x3 passes, fp32 accum.
// Block 128(M)x128(N), 8 warps (2M x 4N), warp tile 64x32, K chunk 64.
// R13: ldmatrix fragment loads + register prefetch of next A chunk.
#define AST 72    // A smem row stride (bf16): rows phase by 16B -> LDSM conflict-free
#define WST 264   // W smem row stride (bf16): rows phase by 16B -> LDSM conflict-free
#define SM_W  (128 * WST * 2)          // 67584 B per half (hi or lo)
#define SM_A  (128 * AST * 2)          // 18432 B per half
#define SM_TOT (2 * SM_W + 2 * SM_A)   // 172032 B

__device__ __forceinline__ void mma_bf16(float c[4], const uint32_t a[4],
                                         const uint32_t b[2]) {
    asm volatile(
        "mma.sync.aligned.m16n8k16.row.col.f32.bf16.bf16.f32 "
        "{%0,%1,%2,%3}, {%4,%5,%6,%7}, {%8,%9}, {%0,%1,%2,%3};"
        : "+f"(c[0]), "+f"(c[1]), "+f"(c[2]), "+f"(c[3])
        : "r"(a[0]), "r"(a[1]), "r"(a[2]), "r"(a[3]), "r"(b[0]), "r"(b[1]));
}

#define LDSM4(r0, r1, r2, r3, addr) \
    asm volatile("ldmatrix.sync.aligned.m8n8.x4.shared.b16 {%0,%1,%2,%3}, [%4];" \
                 : "=r"(r0), "=r"(r1), "=r"(r2), "=r"(r3) : "r"(addr))

template <bool RELU>
__global__ __launch_bounds__(256, 1)
void k_gemm_mma(const float* __restrict__ A,
                const __nv_bfloat16* __restrict__ WThi,
                const __nv_bfloat16* __restrict__ WTlo,
                float* __restrict__ C) {
    extern __shared__ __align__(16) char smem[];
    __nv_bfloat16* sWhi = (__nv_bfloat16*)smem;
    __nv_bfloat16* sWlo = sWhi + 128 * WST;
    __nv_bfloat16* sAhi = sWlo + 128 * WST;
    __nv_bfloat16* sAlo = sAhi + 128 * AST;

    const int tid  = threadIdx.x;
    const int wid  = tid >> 5;
    const int lane = tid & 31;
    const int warpM = wid & 1;
    const int warpN = wid >> 1;
    const int rowBase = blockIdx.x * 128;
    const int nGlob   = blockIdx.y * 128;

    // ---- stage W^T half (128 n-rows x 256 k), hi+lo, once per block ----
    {
        const __nv_bfloat16* srcH = WThi + (size_t)nGlob * 256;
        const __nv_bfloat16* srcL = WTlo + (size_t)nGlob * 256;
        #pragma unroll
        for (int it = 0; it < 16; it++) {
            int idx = tid + it * 256;          // 128*32 16B-chunks
            int n  = idx >> 5;
            int kq = idx & 31;                 // 8-bf16 chunk
            *(uint4*)(sWhi + n * WST + kq * 8) =
                *(const uint4*)(srcH + n * 256 + kq * 8);
            *(uint4*)(sWlo + n * WST + kq * 8) =
                *(const uint4*)(srcL + n * 256 + kq * 8);
        }
    }

    float acc[4][4][4];
    #pragma unroll
    for (int i = 0; i < 4; i++)
        #pragma unroll
        for (int j = 0; j < 4; j++)
            #pragma unroll
            for (int q = 0; q < 4; q++) acc[i][j][q] = 0.f;

    // ldmatrix per-lane base addresses (bytes)
    const uint32_t aHiBase = (uint32_t)__cvta_generic_to_shared(sAhi) +
        (uint32_t)(((warpM * 64 + (lane & 15)) * AST + (lane >> 4) * 8) * 2);
    const uint32_t aLoBase = aHiBase + (uint32_t)(128 * AST * 2);
    const uint32_t bHiBase = (uint32_t)__cvta_generic_to_shared(sWhi) +
        (uint32_t)(((warpN * 32 + ((lane >> 4) << 3) + (lane & 7)) * WST +
                    ((lane >> 3) & 1) * 8) * 2);
    const uint32_t bLoBase = bHiBase + (uint32_t)(128 * WST * 2);

    const int rS = tid >> 1;    // staging row 0..127
    const int hS = tid & 1;     // staging k-half (32 fp32)
    const bool vS = (rowBase + rS) < NN;
    const float* aBase = A + (size_t)(rowBase + rS) * 256 + hS * 32;

    // ---- prefetch A chunk 0 into registers ----
    float4 pf[8];
    #pragma unroll
    for (int q = 0; q < 8; q++)
        pf[q] = vS ? *(const float4*)(aBase + q * 4)
                   : make_float4(0.f, 0.f, 0.f, 0.f);

    for (int kc = 0; kc < 4; kc++) {
        __syncthreads();  // W staged / previous mainloop done with sA
        // ---- convert prefetched A chunk -> split bf16 smem ----
        {
            __nv_bfloat16* dH = sAhi + rS * AST + hS * 32;
            __nv_bfloat16* dL = sAlo + rS * AST + hS * 32;
            #pragma unroll
            for (int q = 0; q < 4; q++) {
                float4 f0 = pf[q * 2];
                float4 f1 = pf[q * 2 + 1];
                if (RELU) {
                    f0.x = fmaxf(f0.x, 0.f); f0.y = fmaxf(f0.y, 0.f);
                    f0.z = fmaxf(f0.z, 0.f); f0.w = fmaxf(f0.w, 0.f);
                    f1.x = fmaxf(f1.x, 0.f); f1.y = fmaxf(f1.y, 0.f);
                    f1.z = fmaxf(f1.z, 0.f); f1.w = fmaxf(f1.w, 0.f);
                }
                __nv_bfloat162 h0 = __float22bfloat162_rn(make_float2(f0.x, f0.y));
                __nv_bfloat162 h1 = __float22bfloat162_rn(make_float2(f0.z, f0.w));
                __nv_bfloat162 h2 = __float22bfloat162_rn(make_float2(f1.x, f1.y));
                __nv_bfloat162 h3 = __float22bfloat162_rn(make_float2(f1.z, f1.w));
                __nv_bfloat162 l0 = __float22bfloat162_rn(make_float2(
                    f0.x - __bfloat162float(h0.x), f0.y - __bfloat162float(h0.y)));
                __nv_bfloat162 l1 = __float22bfloat162_rn(make_float2(
                    f0.z - __bfloat162float(h1.x), f0.w - __bfloat162float(h1.y)));
                __nv_bfloat162 l2 = __float22bfloat162_rn(make_float2(
                    f1.x - __bfloat162float(h2.x), f1.y - __bfloat162float(h2.y)));
                __nv_bfloat162 l3 = __float22bfloat162_rn(make_float2(
                    f1.z - __bfloat162float(h3.x), f1.w - __bfloat162float(h3.y)));
                ((__nv_bfloat162*)(dH + q * 8))[0] = h0;
                ((__nv_bfloat162*)(dH + q * 8))[1] = h1;
                ((__nv_bfloat162*)(dH + q * 8))[2] = h2;
                ((__nv_bfloat162*)(dH + q * 8))[3] = h3;
                ((__nv_bfloat162*)(dL + q * 8))[0] = l0;
                ((__nv_bfloat162*)(dL + q * 8))[1] = l1;
                ((__nv_bfloat162*)(dL + q * 8))[2] = l2;
                ((__nv_bfloat162*)(dL + q * 8))[3] = l3;
            }
        }
        __syncthreads();

        // ---- prefetch next A chunk (LDGs overlap the MMA mainloop) ----
        if (kc < 3) {
            const float* nxt = aBase + (kc + 1) * 64;
            #pragma unroll
            for (int q = 0; q < 8; q++)
                pf[q] = vS ? *(const float4*)(nxt + q * 4)
                           : make_float4(0.f, 0.f, 0.f, 0.f);
        }

        #pragma unroll
        for (int ks = 0; ks < 4; ks++) {
            const uint32_t aOff = (uint32_t)(ks * 32);            // 16 bf16
            const uint32_t bOff = (uint32_t)(kc * 128 + ks * 32); // within W row
            uint32_t ah[4][4], al[4][4], bh[4][2], bl[4][2];
            #pragma unroll
            for (int i = 0; i < 4; i++) {
                LDSM4(ah[i][0], ah[i][1], ah[i][2], ah[i][3],
                      aHiBase + (uint32_t)(i * 16 * AST * 2) + aOff);
                LDSM4(al[i][0], al[i][1], al[i][2], al[i][3],
                      aLoBase + (uint32_t)(i * 16 * AST * 2) + aOff);
            }
            #pragma unroll
            for (int jj = 0; jj < 2; jj++) {
                LDSM4(bh[2 * jj][0], bh[2 * jj][1], bh[2 * jj + 1][0], bh[2 * jj + 1][1],
                      bHiBase + (uint32_t)(jj * 16 * WST * 2) + bOff);
                LDSM4(bl[2 * jj][0], bl[2 * jj][1], bl[2 * jj + 1][0], bl[2 * jj + 1][1],
                      bLoBase + (uint32_t)(jj * 16 * WST * 2) + bOff);
            }
            #pragma unroll
            for (int i = 0; i < 4; i++)
                #pragma unroll
                for (int j = 0; j < 4; j++) {
                    mma_bf16(acc[i][j], ah[i], bh[j]);
                    mma_bf16(acc[i][j], al[i], bh[j]);
                    mma_bf16(acc[i][j], ah[i], bl[j]);
                }
        }
    }

    // ---- epilogue: fragment -> gmem (fp32) ----
    const int g  = lane >> 2;
    const int cc = lane & 3;
    #pragma unroll
    for (int i = 0; i < 4; i++) {
        int row0 = rowBase + warpM * 64 + i * 16 + g;
        int row1 = row0 + 8;
        #pragma unroll
        for (int j = 0; j < 4; j++) {
            int col = nGlob + warpN * 32 + j * 8 + 2 * cc;
            if (row0 < NN)
                *(float2*)(C + (size_t)row0 * 256 + col) =
                    make_float2(acc[i][j][0], acc[i][j][1]);
            if (row1 < NN)
                *(float2*)(C + (size_t)row1 * 256 + col) =
                    make_float2(acc[i][j][2], acc[i][j][3]);
        }
    }
}

// ---------------- aggregation, F=256: warp per node, CSR, no atomics --------
__global__ void k_agg(const float4* __restrict__ T4,
                      const float*  __restrict__ bias,
                      float4* __restrict__ O4) {
    int warp = (blockIdx.x * blockDim.x + threadIdx.x) >> 5;
    int lane = threadIdx.x & 31;
    if (warp >= NN) return;
    int node = warp;
    float ws = g_dis[node];
    ws *= ws;  // self-loop weight dis^2 = 1/deg
    float4 a0 = T4[(size_t)node * 64 + lane];
    float4 a1 = T4[(size_t)node * 64 + lane + 32];
    float4 acc0 = make_float4(a0.x * ws, a0.y * ws, a0.z * ws, a0.w * ws);
    float4 acc1 = make_float4(a1.x * ws, a1.y * ws, a1.z * ws, a1.w * ws);
    int p0 = g_rowstart[node];
    int p1 = g_rowstart[node + 1];
    for (int p = p0; p < p1; p++) {
        int   s = g_esrc[p];
        float w = g_enorm[p];
        float4 v0 = T4[(size_t)s * 64 + lane];
        float4 v1 = T4[(size_t)s * 64 + lane + 32];
        acc0.x = fmaf(v0.x, w, acc0.x); acc0.y = fmaf(v0.y, w, acc0.y);
        acc0.z = fmaf(v0.z, w, acc0.z); acc0.w = fmaf(v0.w, w, acc0.w);
        acc1.x = fmaf(v1.x, w, acc1.x); acc1.y = fmaf(v1.y, w, acc1.y);
        acc1.z = fmaf(v1.z, w, acc1.z); acc1.w = fmaf(v1.w, w, acc1.w);
    }
    float4 b0 = ((const float4*)bias)[lane];
    float4 b1 = ((const float4*)bias)[lane + 32];
    acc0.x += b0.x; acc0.y += b0.y; acc0.z += b0.z; acc0.w += b0.w;
    acc1.x += b1.x; acc1.y += b1.y; acc1.z += b1.z; acc1.w += b1.w;
    O4[(size_t)node * 64 + lane]      = acc0;
    O4[(size_t)node * 64 + lane + 32] = acc1;
}

// ---------------- last layer: t2[N,2] = relu(A) @ W3[256,2] ------------------
__global__ void k_gemm2(const float* __restrict__ A,
                        const float* __restrict__ W3,
                        float* __restrict__ t2) {
    int warp = (blockIdx.x * blockDim.x + threadIdx.x) >> 5;
    int lane = threadIdx.x & 31;
    if (warp >= NN) return;
    const float* row = A + (size_t)warp * 256;
    float s0 = 0.f, s1 = 0.f;
    #pragma unroll
    for (int k = lane; k < 256; k += 32) {
        float h = fmaxf(row[k], 0.f);
        float2 w = ((const float2*)W3)[k];
        s0 = fmaf(h, w.x, s0);
        s1 = fmaf(h, w.y, s1);
    }
    #pragma unroll
    for (int off = 16; off; off >>= 1) {
        s0 += __shfl_xor_sync(0xffffffffu, s0, off);
        s1 += __shfl_xor_sync(0xffffffffu, s1, off);
    }
    if (lane == 0) { t2[warp * 2] = s0; t2[warp * 2 + 1] = s1; }
}

// ---------------- final aggregation (F=2) into d_out -------------------------
__global__ void k_agg2(const float* __restrict__ t2,
                       const float* __restrict__ b3,
                       float* __restrict__ out) {
    int warp = (blockIdx.x * blockDim.x + threadIdx.x) >> 5;
    int lane = threadIdx.x & 31;
    if (warp >= NN) return;
    int node = warp;
    int p0 = g_rowstart[node];
    int p1 = g_rowstart[node + 1];
    float s0 = 0.f, s1 = 0.f;
    for (int p = p0 + lane; p < p1; p += 32) {
        int   s = g_esrc[p];
        float w = g_enorm[p];
        s0 = fmaf(t2[s * 2],     w, s0);
        s1 = fmaf(t2[s * 2 + 1], w, s1);
    }
    #pragma unroll
    for (int off = 16; off; off >>= 1) {
        s0 += __shfl_xor_sync(0xffffffffu, s0, off);
        s1 += __shfl_xor_sync(0xffffffffu, s1, off);
    }
    if (lane == 0) {
        float ws = g_dis[node];
        ws *= ws;
        out[node * 2]     = s0 + t2[node * 2]     * ws + b3[0];
        out[node * 2 + 1] = s1 + t2[node * 2 + 1] * ws + b3[1];
    }
}

// ---------------- launch ------------------------------------------------------
extern "C" void kernel_launch(void* const* d_in, const int* in_sizes, int n_in,
                              void* d_out, int out_size) {
    const float* x  = (const float*)d_in[0];
    const void*  ei = d_in[1];
    const float* W0 = (const float*)d_in[2];
    const float* b0 = (const float*)d_in[3];
    const float* W1 = (const float*)d_in[4];
    const float* b1 = (const float*)d_in[5];
    const float* W2 = (const float*)d_in[6];
    const float* b2 = (const float*)d_in[7];
    const float* W3 = (const float*)d_in[8];
    const float* b3 = (const float*)d_in[9];
    float* out = (float*)d_out;

    float *T, *HA, *HB, *t2;
    __nv_bfloat16 *Whi, *Wlo;
    cudaGetSymbolAddress((void**)&T,   g_T);
    cudaGetSymbolAddress((void**)&HA,  g_HA);
    cudaGetSymbolAddress((void**)&HB,  g_HB);
    cudaGetSymbolAddress((void**)&t2,  g_t2);
    cudaGetSymbolAddress((void**)&Whi, g_Whi);
    cudaGetSymbolAddress((void**)&Wlo, g_Wlo);

    static int smem_set = 0;
    if (!smem_set) {
        cudaFuncSetAttribute(k_gemm_mma<false>,
                             cudaFuncAttributeMaxDynamicSharedMemorySize, SM_TOT);
        cudaFuncSetAttribute(k_gemm_mma<true>,
                             cudaFuncAttributeMaxDynamicSharedMemorySize, SM_TOT);
        smem_set = 1;
    }

    const int nodeBlocks = (NN + 255) / 256;
    const int edgeBlocks = (EE + 255) / 256;
    const int warpBlocks = (NN + 7) / 8;
    dim3 gemmGrid(NTILES, 2);

    // ---- graph preprocessing (4 launches) ----
    k_detect_init<<<nodeBlocks, 256>>>((const int*)ei);
    k_count<<<edgeBlocks, 256>>>(ei);
    k_scan<<<1, 1024>>>();   // also computes g_dis
    k_build<<<edgeBlocks, 256>>>(ei);

    // ---- weight split/transpose (1 launch for all 3 layers) ----
    k_wsplit3<<<768, 256>>>(W0, W1, W2, Whi, Wlo);

    // ---- layer 1 ----
    k_gemm_mma<false><<<gemmGrid, 256, SM_TOT>>>(x, Whi, Wlo, T);
    k_agg<<<warpBlocks, 256>>>((const float4*)T, b0, (float4*)HA);
    // ---- layer 2 ----
    k_gemm_mma<true><<<gemmGrid, 256, SM_TOT>>>(HA, Whi + FF * FF, Wlo + FF * FF, T);
    k_agg<<<warpBlocks, 256>>>((const float4*)T, b1, (float4*)HB);
    // ---- layer 3 ----
    k_gemm_mma<true><<<gemmGrid, 256, SM_TOT>>>(HB, Whi + 2 * FF * FF, Wlo + 2 * FF * FF, T);
    k_agg<<<warpBlocks, 256>>>((const float4*)T, b2, (float4*)HA);
    // ---- layer 4 ----
    k_gemm2<<<warpBlocks, 256>>>(HA, W3, t2);
    k_agg2<<<warpBlocks, 256>>>(t2, b3, out);
}

// round 14
// speedup vs baseline: 1.2290x; 1.1152x over previous
#include <cuda_runtime.h>
#include <cuda_bf16.h>
#include <cuda_fp16.h>
#include <math.h>
#include <stdint.h>

#define NN 50000
#define EE 800000
#define FF 256
#define NTILES 391  // ceil(50000/128)

// ---------------- device scratch (no runtime allocation allowed) ------------
__device__ int   g_is64;
__device__ int   g_cnt[NN];
__device__ int   g_cursor[NN];
__device__ int   g_rowstart[NN + 1];
__device__ float g_dis[NN];
__device__ int   g_esrc[EE];
__device__ float g_enorm[EE];
__device__ __half g_Th[(size_t)NN * FF];     // GEMM output messages (fp16)
__device__ float g_HA[(size_t)NN * FF];
__device__ float g_HB[(size_t)NN * FF];
__device__ float g_t2[NN * 2];
__device__ __nv_bfloat16 g_Whi[3][FF * FF];  // W^T split-high, [n][k]
__device__ __nv_bfloat16 g_Wlo[3][FF * FF];  // W^T split-low,  [n][k]

// ---------------- small helpers ---------------------------------------------
__device__ __forceinline__ int load_edge(const void* ei, long long idx) {
    if (g_is64) return (int)((const long long*)ei)[idx];
    return ((const int*)ei)[idx];
}

// init counters + int64/int32 detection in one launch
__global__ void k_detect_init(const int* p) {
    int i = blockIdx.x * blockDim.x + threadIdx.x;
    if (i < NN) { g_cnt[i] = 0; g_cursor[i] = 0; }
    if (blockIdx.x == 0 && threadIdx.x == 0) {
        int any = 0;
        #pragma unroll
        for (int j = 1; j < 64; j += 2) any |= p[j];
        g_is64 = (any == 0) ? 1 : 0;
    }
}

__global__ void k_count(const void* ei) {
    int e = blockIdx.x * blockDim.x + threadIdx.x;
    if (e >= EE) return;
    int dst = load_edge(ei, (long long)EE + e);
    atomicAdd(&g_cnt[dst], 1);
}

// Exclusive scan of g_cnt -> g_rowstart, fused with g_dis computation.
#define SCAN_PER 49
__global__ void k_scan() {
    __shared__ int warptot[32];
    int tid  = threadIdx.x;
    int lane = tid & 31;
    int wid  = tid >> 5;
    int base = tid * SCAN_PER;
    int sum = 0;
    #pragma unroll 7
    for (int i = 0; i < SCAN_PER; i++) {
        int idx = base + i;
        sum += (idx < NN) ? g_cnt[idx] : 0;
    }
    int x = sum;
    #pragma unroll
    for (int off = 1; off < 32; off <<= 1) {
        int n = __shfl_up_sync(0xffffffffu, x, off);
        if (lane >= off) x += n;
    }
    if (lane == 31) warptot[wid] = x;
    __syncthreads();
    if (wid == 0) {
        int w = warptot[lane];
        #pragma unroll
        for (int off = 1; off < 32; off <<= 1) {
            int n = __shfl_up_sync(0xffffffffu, w, off);
            if (lane >= off) w += n;
        }
        warptot[lane] = w;
    }
    __syncthreads();
    int offset = x - sum;
    if (wid > 0) offset += warptot[wid - 1];
    int running = offset;
    #pragma unroll 7
    for (int i = 0; i < SCAN_PER; i++) {
        int idx = base + i;
        if (idx < NN) {
            int c = g_cnt[idx];
            g_rowstart[idx] = running;
            g_dis[idx] = rsqrtf((float)(c + 1));  // +1 self-loop
            running += c;
        } else if (idx == NN) {
            g_rowstart[idx] = running;
        }
    }
}

__global__ void k_build(const void* ei) {
    int e = blockIdx.x * blockDim.x + threadIdx.x;
    if (e >= EE) return;
    int src = load_edge(ei, e);
    int dst = load_edge(ei, (long long)EE + e);
    float w = g_dis[src] * g_dis[dst];
    int pos = g_rowstart[dst] + atomicAdd(&g_cursor[dst], 1);
    g_esrc[pos]  = src;
    g_enorm[pos] = w;
}

// --------- weight split/transpose for all 3 layers in ONE launch -------------
__global__ void k_wsplit3(const float* __restrict__ W0,
                          const float* __restrict__ W1,
                          const float* __restrict__ W2,
                          __nv_bfloat16* __restrict__ bhi,
                          __nv_bfloat16* __restrict__ blo) {
    int layer = blockIdx.x >> 8;                 // 256 blocks per layer
    const float* W = (layer == 0) ? W0 : (layer == 1) ? W1 : W2;
    int i = (blockIdx.x & 255) * 256 + threadIdx.x;  // i = k*256 + n
    int k = i >> 8, n = i & 255;
    float w = W[i];
    __nv_bfloat16 h = __float2bfloat16_rn(w);
    __nv_bfloat16 l = __float2bfloat16_rn(w - __bfloat162float(h));
    bhi[(size_t)layer * FF * FF + n * 256 + k] = h;
    blo[(size_t)layer * FF * FF + n * 256 + k] = l;
}

// ---------------- mma.sync GEMM (sm_80 path; works on plain sm_103) ---------
// Th[N,256](fp16) = (relu?)A[N,256](fp32) @ W[256,256], split-bf16 x3 passes.
#define AST 72    // A smem row stride (bf16): rows phase by 16B -> LDSM conflict-free
#define WST 264   // W smem row stride (bf16): rows phase by 16B -> LDSM conflict-free
#define SM_W  (128 * WST * 2)          // 67584 B per half (hi or lo)
#define SM_A  (128 * AST * 2)          // 18432 B per half
#define SM_TOT (2 * SM_W + 2 * SM_A)   // 172032 B

__device__ __forceinline__ void mma_bf16(float c[4], const uint32_t a[4],
                                         const uint32_t b[2]) {
    asm volatile(
        "mma.sync.aligned.m16n8k16.row.col.f32.bf16.bf16.f32 "
        "{%0,%1,%2,%3}, {%4,%5,%6,%7}, {%8,%9}, {%0,%1,%2,%3};"
        : "+f"(c[0]), "+f"(c[1]), "+f"(c[2]), "+f"(c[3])
        : "r"(a[0]), "r"(a[1]), "r"(a[2]), "r"(a[3]), "r"(b[0]), "r"(b[1]));
}

#define LDSM4(r0, r1, r2, r3, addr) \
    asm volatile("ldmatrix.sync.aligned.m8n8.x4.shared.b16 {%0,%1,%2,%3}, [%4];" \
                 : "=r"(r0), "=r"(r1), "=r"(r2), "=r"(r3) : "r"(addr))

template <bool RELU>
__global__ __launch_bounds__(256, 1)
void k_gemm_mma(const float* __restrict__ A,
                const __nv_bfloat16* __restrict__ WThi,
                const __nv_bfloat16* __restrict__ WTlo,
                __half* __restrict__ C) {
    extern __shared__ __align__(16) char smem[];
    __nv_bfloat16* sWhi = (__nv_bfloat16*)smem;
    __nv_bfloat16* sWlo = sWhi + 128 * WST;
    __nv_bfloat16* sAhi = sWlo + 128 * WST;
    __nv_bfloat16* sAlo = sAhi + 128 * AST;

    const int tid  = threadIdx.x;
    const int wid  = tid >> 5;
    const int lane = tid & 31;
    const int warpM = wid & 1;
    const int warpN = wid >> 1;
    const int rowBase = blockIdx.x * 128;
    const int nGlob   = blockIdx.y * 128;

    // ---- stage W^T half (128 n-rows x 256 k), hi+lo, once per block ----
    {
        const __nv_bfloat16* srcH = WThi + (size_t)nGlob * 256;
        const __nv_bfloat16* srcL = WTlo + (size_t)nGlob * 256;
        #pragma unroll
        for (int it = 0; it < 16; it++) {
            int idx = tid + it * 256;          // 128*32 16B-chunks
            int n  = idx >> 5;
            int kq = idx & 31;                 // 8-bf16 chunk
            *(uint4*)(sWhi + n * WST + kq * 8) =
                *(const uint4*)(srcH + n * 256 + kq * 8);
            *(uint4*)(sWlo + n * WST + kq * 8) =
                *(const uint4*)(srcL + n * 256 + kq * 8);
        }
    }

    float acc[4][4][4];
    #pragma unroll
    for (int i = 0; i < 4; i++)
        #pragma unroll
        for (int j = 0; j < 4; j++)
            #pragma unroll
            for (int q = 0; q < 4; q++) acc[i][j][q] = 0.f;

    // ldmatrix per-lane base addresses (bytes)
    const uint32_t aHiBase = (uint32_t)__cvta_generic_to_shared(sAhi) +
        (uint32_t)(((warpM * 64 + (lane & 15)) * AST + (lane >> 4) * 8) * 2);
    const uint32_t aLoBase = aHiBase + (uint32_t)(128 * AST * 2);
    const uint32_t bHiBase = (uint32_t)__cvta_generic_to_shared(sWhi) +
        (uint32_t)(((warpN * 32 + ((lane >> 4) << 3) + (lane & 7)) * WST +
                    ((lane >> 3) & 1) * 8) * 2);
    const uint32_t bLoBase = bHiBase + (uint32_t)(128 * WST * 2);

    const int rS = tid >> 1;    // staging row 0..127
    const int hS = tid & 1;     // staging k-half (32 fp32)
    const bool vS = (rowBase + rS) < NN;
    const float* aBase = A + (size_t)(rowBase + rS) * 256 + hS * 32;

    // ---- prefetch A chunk 0 into registers ----
    float4 pf[8];
    #pragma unroll
    for (int q = 0; q < 8; q++)
        pf[q] = vS ? *(const float4*)(aBase + q * 4)
                   : make_float4(0.f, 0.f, 0.f, 0.f);

    for (int kc = 0; kc < 4; kc++) {
        __syncthreads();  // W staged / previous mainloop done with sA
        // ---- convert prefetched A chunk -> split bf16 smem ----
        {
            __nv_bfloat16* dH = sAhi + rS * AST + hS * 32;
            __nv_bfloat16* dL = sAlo + rS * AST + hS * 32;
            #pragma unroll
            for (int q = 0; q < 4; q++) {
                float4 f0 = pf[q * 2];
                float4 f1 = pf[q * 2 + 1];
                if (RELU) {
                    f0.x = fmaxf(f0.x, 0.f); f0.y = fmaxf(f0.y, 0.f);
                    f0.z = fmaxf(f0.z, 0.f); f0.w = fmaxf(f0.w, 0.f);
                    f1.x = fmaxf(f1.x, 0.f); f1.y = fmaxf(f1.y, 0.f);
                    f1.z = fmaxf(f1.z, 0.f); f1.w = fmaxf(f1.w, 0.f);
                }
                __nv_bfloat162 h0 = __float22bfloat162_rn(make_float2(f0.x, f0.y));
                __nv_bfloat162 h1 = __float22bfloat162_rn(make_float2(f0.z, f0.w));
                __nv_bfloat162 h2 = __float22bfloat162_rn(make_float2(f1.x, f1.y));
                __nv_bfloat162 h3 = __float22bfloat162_rn(make_float2(f1.z, f1.w));
                __nv_bfloat162 l0 = __float22bfloat162_rn(make_float2(
                    f0.x - __bfloat162float(h0.x), f0.y - __bfloat162float(h0.y)));
                __nv_bfloat162 l1 = __float22bfloat162_rn(make_float2(
                    f0.z - __bfloat162float(h1.x), f0.w - __bfloat162float(h1.y)));
                __nv_bfloat162 l2 = __float22bfloat162_rn(make_float2(
                    f1.x - __bfloat162float(h2.x), f1.y - __bfloat162float(h2.y)));
                __nv_bfloat162 l3 = __float22bfloat162_rn(make_float2(
                    f1.z - __bfloat162float(h3.x), f1.w - __bfloat162float(h3.y)));
                ((__nv_bfloat162*)(dH + q * 8))[0] = h0;
                ((__nv_bfloat162*)(dH + q * 8))[1] = h1;
                ((__nv_bfloat162*)(dH + q * 8))[2] = h2;
                ((__nv_bfloat162*)(dH + q * 8))[3] = h3;
                ((__nv_bfloat162*)(dL + q * 8))[0] = l0;
                ((__nv_bfloat162*)(dL + q * 8))[1] = l1;
                ((__nv_bfloat162*)(dL + q * 8))[2] = l2;
                ((__nv_bfloat162*)(dL + q * 8))[3] = l3;
            }
        }
        __syncthreads();

        // ---- prefetch next A chunk (LDGs overlap the MMA mainloop) ----
        if (kc < 3) {
            const float* nxt = aBase + (kc + 1) * 64;
            #pragma unroll
            for (int q = 0; q < 8; q++)
                pf[q] = vS ? *(const float4*)(nxt + q * 4)
                           : make_float4(0.f, 0.f, 0.f, 0.f);
        }

        #pragma unroll
        for (int ks = 0; ks < 4; ks++) {
            const uint32_t aOff = (uint32_t)(ks * 32);            // 16 bf16
            const uint32_t bOff = (uint32_t)(kc * 128 + ks * 32); // within W row
            uint32_t ah[4][4], al[4][4], bh[4][2], bl[4][2];
            #pragma unroll
            for (int i = 0; i < 4; i++) {
                LDSM4(ah[i][0], ah[i][1], ah[i][2], ah[i][3],
                      aHiBase + (uint32_t)(i * 16 * AST * 2) + aOff);
                LDSM4(al[i][0], al[i][1], al[i][2], al[i][3],
                      aLoBase + (uint32_t)(i * 16 * AST * 2) + aOff);
            }
            #pragma unroll
            for (int jj = 0; jj < 2; jj++) {
                LDSM4(bh[2 * jj][0], bh[2 * jj][1], bh[2 * jj + 1][0], bh[2 * jj + 1][1],
                      bHiBase + (uint32_t)(jj * 16 * WST * 2) + bOff);
                LDSM4(bl[2 * jj][0], bl[2 * jj][1], bl[2 * jj + 1][0], bl[2 * jj + 1][1],
                      bLoBase + (uint32_t)(jj * 16 * WST * 2) + bOff);
            }
            #pragma unroll
            for (int i = 0; i < 4; i++)
                #pragma unroll
                for (int j = 0; j < 4; j++) {
                    mma_bf16(acc[i][j], ah[i], bh[j]);
                    mma_bf16(acc[i][j], al[i], bh[j]);
                    mma_bf16(acc[i][j], ah[i], bl[j]);
                }
        }
    }

    // ---- epilogue: fragment -> gmem (fp16 messages) ----
    const int g  = lane >> 2;
    const int cc = lane & 3;
    #pragma unroll
    for (int i = 0; i < 4; i++) {
        int row0 = rowBase + warpM * 64 + i * 16 + g;
        int row1 = row0 + 8;
        #pragma unroll
        for (int j = 0; j < 4; j++) {
            int col = nGlob + warpN * 32 + j * 8 + 2 * cc;
            if (row0 < NN)
                *(__half2*)(C + (size_t)row0 * 256 + col) =
                    __floats2half2_rn(acc[i][j][0], acc[i][j][1]);
            if (row1 < NN)
                *(__half2*)(C + (size_t)row1 * 256 + col) =
                    __floats2half2_rn(acc[i][j][2], acc[i][j][3]);
        }
    }
}

// ------- aggregation, F=256 fp16 msgs: warp/node, 1 uint4 per lane/edge -----
__global__ void k_agg_h(const uint4* __restrict__ Th4,
                        const float* __restrict__ bias,
                        float4* __restrict__ O4) {
    int warp = (blockIdx.x * blockDim.x + threadIdx.x) >> 5;
    int lane = threadIdx.x & 31;
    if (warp >= NN) return;
    int node = warp;
    float ws = g_dis[node];
    ws *= ws;  // self-loop weight dis^2 = 1/deg

    float acc[8];
    {
        uint4 sv = Th4[(size_t)node * 32 + lane];
        float2 f0 = __half22float2(*(__half2*)&sv.x);
        float2 f1 = __half22float2(*(__half2*)&sv.y);
        float2 f2 = __half22float2(*(__half2*)&sv.z);
        float2 f3 = __half22float2(*(__half2*)&sv.w);
        acc[0] = f0.x * ws; acc[1] = f0.y * ws;
        acc[2] = f1.x * ws; acc[3] = f1.y * ws;
        acc[4] = f2.x * ws; acc[5] = f2.y * ws;
        acc[6] = f3.x * ws; acc[7] = f3.y * ws;
    }

    int p0 = g_rowstart[node];
    int p1 = g_rowstart[node + 1];
    for (int p = p0; p < p1; p++) {
        int   s = g_esrc[p];
        float w = g_enorm[p];
        uint4 v = Th4[(size_t)s * 32 + lane];
        float2 f0 = __half22float2(*(__half2*)&v.x);
        float2 f1 = __half22float2(*(__half2*)&v.y);
        float2 f2 = __half22float2(*(__half2*)&v.z);
        float2 f3 = __half22float2(*(__half2*)&v.w);
        acc[0] = fmaf(f0.x, w, acc[0]); acc[1] = fmaf(f0.y, w, acc[1]);
        acc[2] = fmaf(f1.x, w, acc[2]); acc[3] = fmaf(f1.y, w, acc[3]);
        acc[4] = fmaf(f2.x, w, acc[4]); acc[5] = fmaf(f2.y, w, acc[5]);
        acc[6] = fmaf(f3.x, w, acc[6]); acc[7] = fmaf(f3.y, w, acc[7]);
    }

    float4 b0 = ((const float4*)bias)[lane * 2];
    float4 b1 = ((const float4*)bias)[lane * 2 + 1];
    float4 o0 = make_float4(acc[0] + b0.x, acc[1] + b0.y,
                            acc[2] + b0.z, acc[3] + b0.w);
    float4 o1 = make_float4(acc[4] + b1.x, acc[5] + b1.y,
                            acc[6] + b1.z, acc[7] + b1.w);
    O4[(size_t)node * 64 + lane * 2]     = o0;
    O4[(size_t)node * 64 + lane * 2 + 1] = o1;
}

// ---------------- last layer: t2[N,2] = relu(A) @ W3[256,2] ------------------
__global__ void k_gemm2(const float* __restrict__ A,
                        const float* __restrict__ W3,
                        float* __restrict__ t2) {
    int warp = (blockIdx.x * blockDim.x + threadIdx.x) >> 5;
    int lane = threadIdx.x & 31;
    if (warp >= NN) return;
    const float* row = A + (size_t)warp * 256;
    float s0 = 0.f, s1 = 0.f;
    #pragma unroll
    for (int k = lane; k < 256; k += 32) {
        float h = fmaxf(row[k], 0.f);
        float2 w = ((const float2*)W3)[k];
        s0 = fmaf(h, w.x, s0);
        s1 = fmaf(h, w.y, s1);
    }
    #pragma unroll
    for (int off = 16; off; off >>= 1) {
        s0 += __shfl_xor_sync(0xffffffffu, s0, off);
        s1 += __shfl_xor_sync(0xffffffffu, s1, off);
    }
    if (lane == 0) { t2[warp * 2] = s0; t2[warp * 2 + 1] = s1; }
}

// ---------------- final aggregation (F=2) into d_out -------------------------
__global__ void k_agg2(const float* __restrict__ t2,
                       const float* __restrict__ b3,
                       float* __restrict__ out) {
    int warp = (blockIdx.x * blockDim.x + threadIdx.x) >> 5;
    int lane = threadIdx.x & 31;
    if (warp >= NN) return;
    int node = warp;
    int p0 = g_rowstart[node];
    int p1 = g_rowstart[node + 1];
    float s0 = 0.f, s1 = 0.f;
    for (int p = p0 + lane; p < p1; p += 32) {
        int   s = g_esrc[p];
        float w = g_enorm[p];
        s0 = fmaf(t2[s * 2],     w, s0);
        s1 = fmaf(t2[s * 2 + 1], w, s1);
    }
    #pragma unroll
    for (int off = 16; off; off >>= 1) {
        s0 += __shfl_xor_sync(0xffffffffu, s0, off);
        s1 += __shfl_xor_sync(0xffffffffu, s1, off);
    }
    if (lane == 0) {
        float ws = g_dis[node];
        ws *= ws;
        out[node * 2]     = s0 + t2[node * 2]     * ws + b3[0];
        out[node * 2 + 1] = s1 + t2[node * 2 + 1] * ws + b3[1];
    }
}

// ---------------- launch ------------------------------------------------------
extern "C" void kernel_launch(void* const* d_in, const int* in_sizes, int n_in,
                              void* d_out, int out_size) {
    const float* x  = (const float*)d_in[0];
    const void*  ei = d_in[1];
    const float* W0 = (const float*)d_in[2];
    const float* b0 = (const float*)d_in[3];
    const float* W1 = (const float*)d_in[4];
    const float* b1 = (const float*)d_in[5];
    const float* W2 = (const float*)d_in[6];
    const float* b2 = (const float*)d_in[7];
    const float* W3 = (const float*)d_in[8];
    const float* b3 = (const float*)d_in[9];
    float* out = (float*)d_out;

    float *HA, *HB, *t2;
    __half* Th;
    __nv_bfloat16 *Whi, *Wlo;
    cudaGetSymbolAddress((void**)&Th,  g_Th);
    cudaGetSymbolAddress((void**)&HA,  g_HA);
    cudaGetSymbolAddress((void**)&HB,  g_HB);
    cudaGetSymbolAddress((void**)&t2,  g_t2);
    cudaGetSymbolAddress((void**)&Whi, g_Whi);
    cudaGetSymbolAddress((void**)&Wlo, g_Wlo);

    static int smem_set = 0;
    if (!smem_set) {
        cudaFuncSetAttribute(k_gemm_mma<false>,
                             cudaFuncAttributeMaxDynamicSharedMemorySize, SM_TOT);
        cudaFuncSetAttribute(k_gemm_mma<true>,
                             cudaFuncAttributeMaxDynamicSharedMemorySize, SM_TOT);
        smem_set = 1;
    }

    const int nodeBlocks = (NN + 255) / 256;
    const int edgeBlocks = (EE + 255) / 256;
    const int warpBlocks = (NN + 7) / 8;
    dim3 gemmGrid(NTILES, 2);

    // ---- graph preprocessing (4 launches) ----
    k_detect_init<<<nodeBlocks, 256>>>((const int*)ei);
    k_count<<<edgeBlocks, 256>>>(ei);
    k_scan<<<1, 1024>>>();   // also computes g_dis
    k_build<<<edgeBlocks, 256>>>(ei);

    // ---- weight split/transpose (1 launch for all 3 layers) ----
    k_wsplit3<<<768, 256>>>(W0, W1, W2, Whi, Wlo);

    // ---- layer 1 ----
    k_gemm_mma<false><<<gemmGrid, 256, SM_TOT>>>(x, Whi, Wlo, Th);
    k_agg_h<<<warpBlocks, 256>>>((const uint4*)Th, b0, (float4*)HA);
    // ---- layer 2 ----
    k_gemm_mma<true><<<gemmGrid, 256, SM_TOT>>>(HA, Whi + FF * FF, Wlo + FF * FF, Th);
    k_agg_h<<<warpBlocks, 256>>>((const uint4*)Th, b1, (float4*)HB);
    // ---- layer 3 ----
    k_gemm_mma<true><<<gemmGrid, 256, SM_TOT>>>(HB, Whi + 2 * FF * FF, Wlo + 2 * FF * FF, Th);
    k_agg_h<<<warpBlocks, 256>>>((const uint4*)Th, b2, (float4*)HA);
    // ---- layer 4 ----
    k_gemm2<<<warpBlocks, 256>>>(HA, W3, t2);
    k_agg2<<<warpBlocks, 256>>>(t2, b3, out);
}

// round 15
// speedup vs baseline: 1.4346x; 1.1673x over previous
#include <cuda_runtime.h>
#include <cuda_bf16.h>
#include <cuda_fp16.h>
#include <math.h>
#include <stdint.h>

#define NN 50000
#define EE 800000
#define FF 256
#define NTILES 391  // ceil(50000/128)

// ---------------- device scratch (no runtime allocation allowed) ------------
__device__ int   g_is64;
__device__ int   g_cnt[NN];
__device__ int   g_cursor[NN];
__device__ int   g_rowstart[NN + 1];
__device__ float g_dis[NN];
__device__ int   g_esrc[EE];
__device__ float g_enorm[EE];
__device__ __half g_Th[(size_t)NN * FF];     // GEMM output messages (fp16)
__device__ __half g_HA[(size_t)NN * FF];     // hidden activations (fp16)
__device__ __half g_HB[(size_t)NN * FF];
__device__ float g_t2[NN * 2];
__device__ __nv_bfloat16 g_Whi[FF * FF];     // layer-0 W^T split-high (bf16)
__device__ __nv_bfloat16 g_Wlo[FF * FF];     // layer-0 W^T split-low  (bf16)
__device__ __half g_Wh16[2][FF * FF];        // layers 1,2 W^T hi (fp16)
__device__ __half g_Wl16[2][FF * FF];        // layers 1,2 W^T lo*2048 (fp16)

// ---------------- small helpers ---------------------------------------------
__device__ __forceinline__ int load_edge(const void* ei, long long idx) {
    if (g_is64) return (int)((const long long*)ei)[idx];
    return ((const int*)ei)[idx];
}

__global__ void k_detect_init(const int* p) {
    int i = blockIdx.x * blockDim.x + threadIdx.x;
    if (i < NN) { g_cnt[i] = 0; g_cursor[i] = 0; }
    if (blockIdx.x == 0 && threadIdx.x == 0) {
        int any = 0;
        #pragma unroll
        for (int j = 1; j < 64; j += 2) any |= p[j];
        g_is64 = (any == 0) ? 1 : 0;
    }
}

__global__ void k_count(const void* ei) {
    int e = blockIdx.x * blockDim.x + threadIdx.x;
    if (e >= EE) return;
    int dst = load_edge(ei, (long long)EE + e);
    atomicAdd(&g_cnt[dst], 1);
}

#define SCAN_PER 49
__global__ void k_scan() {
    __shared__ int warptot[32];
    int tid  = threadIdx.x;
    int lane = tid & 31;
    int wid  = tid >> 5;
    int base = tid * SCAN_PER;
    int sum = 0;
    #pragma unroll 7
    for (int i = 0; i < SCAN_PER; i++) {
        int idx = base + i;
        sum += (idx < NN) ? g_cnt[idx] : 0;
    }
    int x = sum;
    #pragma unroll
    for (int off = 1; off < 32; off <<= 1) {
        int n = __shfl_up_sync(0xffffffffu, x, off);
        if (lane >= off) x += n;
    }
    if (lane == 31) warptot[wid] = x;
    __syncthreads();
    if (wid == 0) {
        int w = warptot[lane];
        #pragma unroll
        for (int off = 1; off < 32; off <<= 1) {
            int n = __shfl_up_sync(0xffffffffu, w, off);
            if (lane >= off) w += n;
        }
        warptot[lane] = w;
    }
    __syncthreads();
    int offset = x - sum;
    if (wid > 0) offset += warptot[wid - 1];
    int running = offset;
    #pragma unroll 7
    for (int i = 0; i < SCAN_PER; i++) {
        int idx = base + i;
        if (idx < NN) {
            int c = g_cnt[idx];
            g_rowstart[idx] = running;
            g_dis[idx] = rsqrtf((float)(c + 1));  // +1 self-loop
            running += c;
        } else if (idx == NN) {
            g_rowstart[idx] = running;
        }
    }
}

__global__ void k_build(const void* ei) {
    int e = blockIdx.x * blockDim.x + threadIdx.x;
    if (e >= EE) return;
    int src = load_edge(ei, e);
    int dst = load_edge(ei, (long long)EE + e);
    float w = g_dis[src] * g_dis[dst];
    int pos = g_rowstart[dst] + atomicAdd(&g_cursor[dst], 1);
    g_esrc[pos]  = src;
    g_enorm[pos] = w;
}

// --- weight split/transpose: layer 0 -> bf16 hi/lo; layers 1,2 -> f16 hi/lo --
__global__ void k_wsplit3(const float* __restrict__ W0,
                          const float* __restrict__ W1,
                          const float* __restrict__ W2,
                          __nv_bfloat16* __restrict__ bhi,
                          __nv_bfloat16* __restrict__ blo,
                          __half* __restrict__ fhi,
                          __half* __restrict__ flo) {
    int layer = blockIdx.x >> 8;                     // 256 blocks per layer
    int i = (blockIdx.x & 255) * 256 + threadIdx.x;  // i = k*256 + n
    int k = i >> 8, n = i & 255;
    if (layer == 0) {
        float w = W0[i];
        __nv_bfloat16 h = __float2bfloat16_rn(w);
        __nv_bfloat16 l = __float2bfloat16_rn(w - __bfloat162float(h));
        bhi[n * 256 + k] = h;
        blo[n * 256 + k] = l;
    } else {
        const float* W = (layer == 1) ? W1 : W2;
        float w = W[i];
        __half h = __float2half_rn(w);
        __half l = __float2half_rn((w - __half2float(h)) * 2048.f);
        size_t off = (size_t)(layer - 1) * FF * FF + n * 256 + k;
        fhi[off] = h;
        flo[off] = l;
    }
}

// ---------------- shared GEMM constants --------------------------------------
#define AST 72    // A smem row stride (16-bit elems): +16B/row phase, LDSM clean
#define WST 264   // W smem row stride
#define SM_W   (128 * WST * 2)
#define SM_A   (128 * AST * 2)
#define SM_TOT  (2 * SM_W + 2 * SM_A)   // bf16 path: 172032 B
#define SM_TOTH (2 * SM_W + SM_A)       // f16 path:  153600 B

__device__ __forceinline__ void mma_bf16(float c[4], const uint32_t a[4],
                                         const uint32_t b[2]) {
    asm volatile(
        "mma.sync.aligned.m16n8k16.row.col.f32.bf16.bf16.f32 "
        "{%0,%1,%2,%3}, {%4,%5,%6,%7}, {%8,%9}, {%0,%1,%2,%3};"
        : "+f"(c[0]), "+f"(c[1]), "+f"(c[2]), "+f"(c[3])
        : "r"(a[0]), "r"(a[1]), "r"(a[2]), "r"(a[3]), "r"(b[0]), "r"(b[1]));
}
__device__ __forceinline__ void mma_f16(float c[4], const uint32_t a[4],
                                        const uint32_t b[2]) {
    asm volatile(
        "mma.sync.aligned.m16n8k16.row.col.f32.f16.f16.f32 "
        "{%0,%1,%2,%3}, {%4,%5,%6,%7}, {%8,%9}, {%0,%1,%2,%3};"
        : "+f"(c[0]), "+f"(c[1]), "+f"(c[2]), "+f"(c[3])
        : "r"(a[0]), "r"(a[1]), "r"(a[2]), "r"(a[3]), "r"(b[0]), "r"(b[1]));
}
#define LDSM4(r0, r1, r2, r3, addr) \
    asm volatile("ldmatrix.sync.aligned.m8n8.x4.shared.b16 {%0,%1,%2,%3}, [%4];" \
                 : "=r"(r0), "=r"(r1), "=r"(r2), "=r"(r3) : "r"(addr))

// -------- layer-1 GEMM: fp32 A, split-bf16 x3 (proven R13 kernel) -----------
__global__ __launch_bounds__(256, 1)
void k_gemm_mma(const float* __restrict__ A,
                const __nv_bfloat16* __restrict__ WThi,
                const __nv_bfloat16* __restrict__ WTlo,
                __half* __restrict__ C) {
    extern __shared__ __align__(16) char smem[];
    __nv_bfloat16* sWhi = (__nv_bfloat16*)smem;
    __nv_bfloat16* sWlo = sWhi + 128 * WST;
    __nv_bfloat16* sAhi = sWlo + 128 * WST;
    __nv_bfloat16* sAlo = sAhi + 128 * AST;

    const int tid  = threadIdx.x;
    const int wid  = tid >> 5;
    const int lane = tid & 31;
    const int warpM = wid & 1;
    const int warpN = wid >> 1;
    const int rowBase = blockIdx.x * 128;
    const int nGlob   = blockIdx.y * 128;

    {
        const __nv_bfloat16* srcH = WThi + (size_t)nGlob * 256;
        const __nv_bfloat16* srcL = WTlo + (size_t)nGlob * 256;
        #pragma unroll
        for (int it = 0; it < 16; it++) {
            int idx = tid + it * 256;
            int n  = idx >> 5;
            int kq = idx & 31;
            *(uint4*)(sWhi + n * WST + kq * 8) =
                *(const uint4*)(srcH + n * 256 + kq * 8);
            *(uint4*)(sWlo + n * WST + kq * 8) =
                *(const uint4*)(srcL + n * 256 + kq * 8);
        }
    }

    float acc[4][4][4];
    #pragma unroll
    for (int i = 0; i < 4; i++)
        #pragma unroll
        for (int j = 0; j < 4; j++)
            #pragma unroll
            for (int q = 0; q < 4; q++) acc[i][j][q] = 0.f;

    const uint32_t aHiBase = (uint32_t)__cvta_generic_to_shared(sAhi) +
        (uint32_t)(((warpM * 64 + (lane & 15)) * AST + (lane >> 4) * 8) * 2);
    const uint32_t aLoBase = aHiBase + (uint32_t)(128 * AST * 2);
    const uint32_t bHiBase = (uint32_t)__cvta_generic_to_shared(sWhi) +
        (uint32_t)(((warpN * 32 + ((lane >> 4) << 3) + (lane & 7)) * WST +
                    ((lane >> 3) & 1) * 8) * 2);
    const uint32_t bLoBase = bHiBase + (uint32_t)(128 * WST * 2);

    const int rS = tid >> 1;
    const int hS = tid & 1;
    const bool vS = (rowBase + rS) < NN;
    const float* aBase = A + (size_t)(rowBase + rS) * 256 + hS * 32;

    float4 pf[8];
    #pragma unroll
    for (int q = 0; q < 8; q++)
        pf[q] = vS ? *(const float4*)(aBase + q * 4)
                   : make_float4(0.f, 0.f, 0.f, 0.f);

    for (int kc = 0; kc < 4; kc++) {
        __syncthreads();
        {
            __nv_bfloat16* dH = sAhi + rS * AST + hS * 32;
            __nv_bfloat16* dL = sAlo + rS * AST + hS * 32;
            #pragma unroll
            for (int q = 0; q < 4; q++) {
                float4 f0 = pf[q * 2];
                float4 f1 = pf[q * 2 + 1];
                __nv_bfloat162 h0 = __float22bfloat162_rn(make_float2(f0.x, f0.y));
                __nv_bfloat162 h1 = __float22bfloat162_rn(make_float2(f0.z, f0.w));
                __nv_bfloat162 h2 = __float22bfloat162_rn(make_float2(f1.x, f1.y));
                __nv_bfloat162 h3 = __float22bfloat162_rn(make_float2(f1.z, f1.w));
                __nv_bfloat162 l0 = __float22bfloat162_rn(make_float2(
                    f0.x - __bfloat162float(h0.x), f0.y - __bfloat162float(h0.y)));
                __nv_bfloat162 l1 = __float22bfloat162_rn(make_float2(
                    f0.z - __bfloat162float(h1.x), f0.w - __bfloat162float(h1.y)));
                __nv_bfloat162 l2 = __float22bfloat162_rn(make_float2(
                    f1.x - __bfloat162float(h2.x), f1.y - __bfloat162float(h2.y)));
                __nv_bfloat162 l3 = __float22bfloat162_rn(make_float2(
                    f1.z - __bfloat162float(h3.x), f1.w - __bfloat162float(h3.y)));
                ((__nv_bfloat162*)(dH + q * 8))[0] = h0;
                ((__nv_bfloat162*)(dH + q * 8))[1] = h1;
                ((__nv_bfloat162*)(dH + q * 8))[2] = h2;
                ((__nv_bfloat162*)(dH + q * 8))[3] = h3;
                ((__nv_bfloat162*)(dL + q * 8))[0] = l0;
                ((__nv_bfloat162*)(dL + q * 8))[1] = l1;
                ((__nv_bfloat162*)(dL + q * 8))[2] = l2;
                ((__nv_bfloat162*)(dL + q * 8))[3] = l3;
            }
        }
        __syncthreads();

        if (kc < 3) {
            const float* nxt = aBase + (kc + 1) * 64;
            #pragma unroll
            for (int q = 0; q < 8; q++)
                pf[q] = vS ? *(const float4*)(nxt + q * 4)
                           : make_float4(0.f, 0.f, 0.f, 0.f);
        }

        #pragma unroll
        for (int ks = 0; ks < 4; ks++) {
            const uint32_t aOff = (uint32_t)(ks * 32);
            const uint32_t bOff = (uint32_t)(kc * 128 + ks * 32);
            uint32_t ah[4][4], al[4][4], bh[4][2], bl[4][2];
            #pragma unroll
            for (int i = 0; i < 4; i++) {
                LDSM4(ah[i][0], ah[i][1], ah[i][2], ah[i][3],
                      aHiBase + (uint32_t)(i * 16 * AST * 2) + aOff);
                LDSM4(al[i][0], al[i][1], al[i][2], al[i][3],
                      aLoBase + (uint32_t)(i * 16 * AST * 2) + aOff);
            }
            #pragma unroll
            for (int jj = 0; jj < 2; jj++) {
                LDSM4(bh[2 * jj][0], bh[2 * jj][1], bh[2 * jj + 1][0], bh[2 * jj + 1][1],
                      bHiBase + (uint32_t)(jj * 16 * WST * 2) + bOff);
                LDSM4(bl[2 * jj][0], bl[2 * jj][1], bl[2 * jj + 1][0], bl[2 * jj + 1][1],
                      bLoBase + (uint32_t)(jj * 16 * WST * 2) + bOff);
            }
            #pragma unroll
            for (int i = 0; i < 4; i++)
                #pragma unroll
                for (int j = 0; j < 4; j++) {
                    mma_bf16(acc[i][j], ah[i], bh[j]);
                    mma_bf16(acc[i][j], al[i], bh[j]);
                    mma_bf16(acc[i][j], ah[i], bl[j]);
                }
        }
    }

    const int g  = lane >> 2;
    const int cc = lane & 3;
    #pragma unroll
    for (int i = 0; i < 4; i++) {
        int row0 = rowBase + warpM * 64 + i * 16 + g;
        int row1 = row0 + 8;
        #pragma unroll
        for (int j = 0; j < 4; j++) {
            int col = nGlob + warpN * 32 + j * 8 + 2 * cc;
            if (row0 < NN)
                *(__half2*)(C + (size_t)row0 * 256 + col) =
                    __floats2half2_rn(acc[i][j][0], acc[i][j][1]);
            if (row1 < NN)
                *(__half2*)(C + (size_t)row1 * 256 + col) =
                    __floats2half2_rn(acc[i][j][2], acc[i][j][3]);
        }
    }
}

// -------- layers 2,3 GEMM: fp16 A (exact), W split f16 x2, relu fused --------
__global__ __launch_bounds__(256, 1)
void k_gemm_h(const __half* __restrict__ A,
              const __half* __restrict__ WThi,
              const __half* __restrict__ WTlo,
              __half* __restrict__ C) {
    extern __shared__ __align__(16) char smem[];
    __half* sWhi = (__half*)smem;
    __half* sWlo = sWhi + 128 * WST;
    __half* sA   = sWlo + 128 * WST;

    const int tid  = threadIdx.x;
    const int wid  = tid >> 5;
    const int lane = tid & 31;
    const int warpM = wid & 1;
    const int warpN = wid >> 1;
    const int rowBase = blockIdx.x * 128;
    const int nGlob   = blockIdx.y * 128;

    {
        const __half* srcH = WThi + (size_t)nGlob * 256;
        const __half* srcL = WTlo + (size_t)nGlob * 256;
        #pragma unroll
        for (int it = 0; it < 16; it++) {
            int idx = tid + it * 256;
            int n  = idx >> 5;
            int kq = idx & 31;
            *(uint4*)(sWhi + n * WST + kq * 8) =
                *(const uint4*)(srcH + n * 256 + kq * 8);
            *(uint4*)(sWlo + n * WST + kq * 8) =
                *(const uint4*)(srcL + n * 256 + kq * 8);
        }
    }

    float acch[4][4][4], accl[4][4][4];
    #pragma unroll
    for (int i = 0; i < 4; i++)
        #pragma unroll
        for (int j = 0; j < 4; j++)
            #pragma unroll
            for (int q = 0; q < 4; q++) { acch[i][j][q] = 0.f; accl[i][j][q] = 0.f; }

    const uint32_t aBaseSm = (uint32_t)__cvta_generic_to_shared(sA) +
        (uint32_t)(((warpM * 64 + (lane & 15)) * AST + (lane >> 4) * 8) * 2);
    const uint32_t bHiBase = (uint32_t)__cvta_generic_to_shared(sWhi) +
        (uint32_t)(((warpN * 32 + ((lane >> 4) << 3) + (lane & 7)) * WST +
                    ((lane >> 3) & 1) * 8) * 2);
    const uint32_t bLoBase = bHiBase + (uint32_t)(128 * WST * 2);

    const int rS = tid >> 1;
    const int hS = tid & 1;
    const bool vS = (rowBase + rS) < NN;
    const __half* aBase = A + (size_t)(rowBase + rS) * 256 + hS * 32;
    const uint4 z4 = make_uint4(0, 0, 0, 0);

    uint4 pf[4];  // 32 halves = one 64-col chunk half
    #pragma unroll
    for (int q = 0; q < 4; q++)
        pf[q] = vS ? *(const uint4*)((const char*)aBase + q * 16) : z4;

    const __half2 zh = __float2half2_rn(0.f);
    for (int kc = 0; kc < 4; kc++) {
        __syncthreads();
        {
            __half* dst = sA + rS * AST + hS * 32;
            #pragma unroll
            for (int q = 0; q < 4; q++) {
                uint4 v = pf[q];
                __half2* h2 = (__half2*)&v;
                h2[0] = __hmax2(h2[0], zh);
                h2[1] = __hmax2(h2[1], zh);
                h2[2] = __hmax2(h2[2], zh);
                h2[3] = __hmax2(h2[3], zh);
                *(uint4*)(dst + q * 8) = v;
            }
        }
        __syncthreads();

        if (kc < 3) {
            const __half* nxt = aBase + (kc + 1) * 64;
            #pragma unroll
            for (int q = 0; q < 4; q++)
                pf[q] = vS ? *(const uint4*)((const char*)nxt + q * 16) : z4;
        }

        #pragma unroll
        for (int ks = 0; ks < 4; ks++) {
            const uint32_t aOff = (uint32_t)(ks * 32);
            const uint32_t bOff = (uint32_t)(kc * 128 + ks * 32);
            uint32_t ah[4][4], bh[4][2], bl[4][2];
            #pragma unroll
            for (int i = 0; i < 4; i++)
                LDSM4(ah[i][0], ah[i][1], ah[i][2], ah[i][3],
                      aBaseSm + (uint32_t)(i * 16 * AST * 2) + aOff);
            #pragma unroll
            for (int jj = 0; jj < 2; jj++) {
                LDSM4(bh[2 * jj][0], bh[2 * jj][1], bh[2 * jj + 1][0], bh[2 * jj + 1][1],
                      bHiBase + (uint32_t)(jj * 16 * WST * 2) + bOff);
                LDSM4(bl[2 * jj][0], bl[2 * jj][1], bl[2 * jj + 1][0], bl[2 * jj + 1][1],
                      bLoBase + (uint32_t)(jj * 16 * WST * 2) + bOff);
            }
            #pragma unroll
            for (int i = 0; i < 4; i++)
                #pragma unroll
                for (int j = 0; j < 4; j++) {
                    mma_f16(acch[i][j], ah[i], bh[j]);
                    mma_f16(accl[i][j], ah[i], bl[j]);
                }
        }
    }

    const float S = 1.f / 2048.f;
    const int g  = lane >> 2;
    const int cc = lane & 3;
    #pragma unroll
    for (int i = 0; i < 4; i++) {
        int row0 = rowBase + warpM * 64 + i * 16 + g;
        int row1 = row0 + 8;
        #pragma unroll
        for (int j = 0; j < 4; j++) {
            int col = nGlob + warpN * 32 + j * 8 + 2 * cc;
            if (row0 < NN)
                *(__half2*)(C + (size_t)row0 * 256 + col) = __floats2half2_rn(
                    fmaf(accl[i][j][0], S, acch[i][j][0]),
                    fmaf(accl[i][j][1], S, acch[i][j][1]));
            if (row1 < NN)
                *(__half2*)(C + (size_t)row1 * 256 + col) = __floats2half2_rn(
                    fmaf(accl[i][j][2], S, acch[i][j][2]),
                    fmaf(accl[i][j][3], S, acch[i][j][3]));
        }
    }
}

// ------- aggregation, fp16 msgs -> fp16 H (+bias, relu deferred) -------------
__global__ void k_agg_h(const uint4* __restrict__ Th4,
                        const float* __restrict__ bias,
                        __half* __restrict__ O) {
    int warp = (blockIdx.x * blockDim.x + threadIdx.x) >> 5;
    int lane = threadIdx.x & 31;
    if (warp >= NN) return;
    int node = warp;
    float ws = g_dis[node];
    ws *= ws;  // self-loop weight dis^2 = 1/deg

    float acc[8];
    {
        uint4 sv = Th4[(size_t)node * 32 + lane];
        float2 f0 = __half22float2(*(__half2*)&sv.x);
        float2 f1 = __half22float2(*(__half2*)&sv.y);
        float2 f2 = __half22float2(*(__half2*)&sv.z);
        float2 f3 = __half22float2(*(__half2*)&sv.w);
        acc[0] = f0.x * ws; acc[1] = f0.y * ws;
        acc[2] = f1.x * ws; acc[3] = f1.y * ws;
        acc[4] = f2.x * ws; acc[5] = f2.y * ws;
        acc[6] = f3.x * ws; acc[7] = f3.y * ws;
    }

    int p0 = g_rowstart[node];
    int p1 = g_rowstart[node + 1];
    for (int p = p0; p < p1; p++) {
        int   s = g_esrc[p];
        float w = g_enorm[p];
        uint4 v = Th4[(size_t)s * 32 + lane];
        float2 f0 = __half22float2(*(__half2*)&v.x);
        float2 f1 = __half22float2(*(__half2*)&v.y);
        float2 f2 = __half22float2(*(__half2*)&v.z);
        float2 f3 = __half22float2(*(__half2*)&v.w);
        acc[0] = fmaf(f0.x, w, acc[0]); acc[1] = fmaf(f0.y, w, acc[1]);
        acc[2] = fmaf(f1.x, w, acc[2]); acc[3] = fmaf(f1.y, w, acc[3]);
        acc[4] = fmaf(f2.x, w, acc[4]); acc[5] = fmaf(f2.y, w, acc[5]);
        acc[6] = fmaf(f3.x, w, acc[6]); acc[7] = fmaf(f3.y, w, acc[7]);
    }

    float4 b0 = ((const float4*)bias)[lane * 2];
    float4 b1 = ((const float4*)bias)[lane * 2 + 1];
    uint4 ov;
    *(__half2*)&ov.x = __floats2half2_rn(acc[0] + b0.x, acc[1] + b0.y);
    *(__half2*)&ov.y = __floats2half2_rn(acc[2] + b0.z, acc[3] + b0.w);
    *(__half2*)&ov.z = __floats2half2_rn(acc[4] + b1.x, acc[5] + b1.y);
    *(__half2*)&ov.w = __floats2half2_rn(acc[6] + b1.z, acc[7] + b1.w);
    *(uint4*)(O + (size_t)node * 256 + lane * 8) = ov;
}

// ---------------- last layer: t2[N,2] = relu(A) @ W3[256,2] ------------------
__global__ void k_gemm2(const __half* __restrict__ A,
                        const float* __restrict__ W3,
                        float* __restrict__ t2) {
    int warp = (blockIdx.x * blockDim.x + threadIdx.x) >> 5;
    int lane = threadIdx.x & 31;
    if (warp >= NN) return;
    const __half* row = A + (size_t)warp * 256;
    float s0 = 0.f, s1 = 0.f;
    #pragma unroll
    for (int k = lane; k < 256; k += 32) {
        float h = fmaxf(__half2float(row[k]), 0.f);
        float2 w = ((const float2*)W3)[k];
        s0 = fmaf(h, w.x, s0);
        s1 = fmaf(h, w.y, s1);
    }
    #pragma unroll
    for (int off = 16; off; off >>= 1) {
        s0 += __shfl_xor_sync(0xffffffffu, s0, off);
        s1 += __shfl_xor_sync(0xffffffffu, s1, off);
    }
    if (lane == 0) { t2[warp * 2] = s0; t2[warp * 2 + 1] = s1; }
}

// ---------------- final aggregation (F=2) into d_out -------------------------
__global__ void k_agg2(const float* __restrict__ t2,
                       const float* __restrict__ b3,
                       float* __restrict__ out) {
    int warp = (blockIdx.x * blockDim.x + threadIdx.x) >> 5;
    int lane = threadIdx.x & 31;
    if (warp >= NN) return;
    int node = warp;
    int p0 = g_rowstart[node];
    int p1 = g_rowstart[node + 1];
    float s0 = 0.f, s1 = 0.f;
    for (int p = p0 + lane; p < p1; p += 32) {
        int   s = g_esrc[p];
        float w = g_enorm[p];
        s0 = fmaf(t2[s * 2],     w, s0);
        s1 = fmaf(t2[s * 2 + 1], w, s1);
    }
    #pragma unroll
    for (int off = 16; off; off >>= 1) {
        s0 += __shfl_xor_sync(0xffffffffu, s0, off);
        s1 += __shfl_xor_sync(0xffffffffu, s1, off);
    }
    if (lane == 0) {
        float ws = g_dis[node];
        ws *= ws;
        out[node * 2]     = s0 + t2[node * 2]     * ws + b3[0];
        out[node * 2 + 1] = s1 + t2[node * 2 + 1] * ws + b3[1];
    }
}

// ---------------- launch ------------------------------------------------------
extern "C" void kernel_launch(void* const* d_in, const int* in_sizes, int n_in,
                              void* d_out, int out_size) {
    const float* x  = (const float*)d_in[0];
    const void*  ei = d_in[1];
    const float* W0 = (const float*)d_in[2];
    const float* b0 = (const float*)d_in[3];
    const float* W1 = (const float*)d_in[4];
    const float* b1 = (const float*)d_in[5];
    const float* W2 = (const float*)d_in[6];
    const float* b2 = (const float*)d_in[7];
    const float* W3 = (const float*)d_in[8];
    const float* b3 = (const float*)d_in[9];
    float* out = (float*)d_out;

    float *t2;
    __half *Th, *HA, *HB, *Wh16, *Wl16;
    __nv_bfloat16 *Whi, *Wlo;
    cudaGetSymbolAddress((void**)&Th,   g_Th);
    cudaGetSymbolAddress((void**)&HA,   g_HA);
    cudaGetSymbolAddress((void**)&HB,   g_HB);
    cudaGetSymbolAddress((void**)&t2,   g_t2);
    cudaGetSymbolAddress((void**)&Whi,  g_Whi);
    cudaGetSymbolAddress((void**)&Wlo,  g_Wlo);
    cudaGetSymbolAddress((void**)&Wh16, g_Wh16);
    cudaGetSymbolAddress((void**)&Wl16, g_Wl16);

    static int smem_set = 0;
    if (!smem_set) {
        cudaFuncSetAttribute(k_gemm_mma,
                             cudaFuncAttributeMaxDynamicSharedMemorySize, SM_TOT);
        cudaFuncSetAttribute(k_gemm_h,
                             cudaFuncAttributeMaxDynamicSharedMemorySize, SM_TOTH);
        smem_set = 1;
    }

    const int nodeBlocks = (NN + 255) / 256;
    const int edgeBlocks = (EE + 255) / 256;
    const int warpBlocks = (NN + 7) / 8;
    dim3 gemmGrid(NTILES, 2);

    // ---- graph preprocessing ----
    k_detect_init<<<nodeBlocks, 256>>>((const int*)ei);
    k_count<<<edgeBlocks, 256>>>(ei);
    k_scan<<<1, 1024>>>();
    k_build<<<edgeBlocks, 256>>>(ei);

    // ---- weight split/transpose (1 launch, all 3 hidden layers) ----
    k_wsplit3<<<768, 256>>>(W0, W1, W2, Whi, Wlo, Wh16, Wl16);

    // ---- layer 1 (fp32 x -> bf16 3-pass) ----
    k_gemm_mma<<<gemmGrid, 256, SM_TOT>>>(x, Whi, Wlo, Th);
    k_agg_h<<<warpBlocks, 256>>>((const uint4*)Th, b0, HA);
    // ---- layer 2 (fp16 A exact, f16 2-pass, relu fused) ----
    k_gemm_h<<<gemmGrid, 256, SM_TOTH>>>(HA, Wh16, Wl16, Th);
    k_agg_h<<<warpBlocks, 256>>>((const uint4*)Th, b1, HB);
    // ---- layer 3 ----
    k_gemm_h<<<gemmGrid, 256, SM_TOTH>>>(HB, Wh16 + FF * FF, Wl16 + FF * FF, Th);
    k_agg_h<<<warpBlocks, 256>>>((const uint4*)Th, b2, HA);
    // ---- layer 4 ----
    k_gemm2<<<warpBlocks, 256>>>(HA, W3, t2);
    k_agg2<<<warpBlocks, 256>>>(t2, b3, out);
}

// round 16
// speedup vs baseline: 1.4734x; 1.0271x over previous
#include <cuda_runtime.h>
#include <cuda_fp16.h>
#include <math.h>
#include <stdint.h>

#define NN 50000
#define EE 800000
#define FF 256
#define NTILES 391  // ceil(50000/128)

// ---------------- device scratch (no runtime allocation allowed) ------------
__device__ int   g_is64;
__device__ int   g_cnt[NN];
__device__ int   g_cursor[NN];
__device__ int   g_rowstart[NN + 1];
__device__ float g_dis[NN];
__device__ int   g_esrc[EE];
__device__ float g_enorm[EE];
__device__ __half g_X16[(size_t)NN * FF];    // fp16-quantized input x
__device__ __half g_Th[(size_t)NN * FF];     // GEMM output messages (fp16)
__device__ __half g_HA[(size_t)NN * FF];     // hidden activations (fp16)
__device__ __half g_HB[(size_t)NN * FF];
__device__ float g_t2[NN * 2];
__device__ __half g_Wh16[3][FF * FF];        // W^T hi (fp16), layers 0-2
__device__ __half g_Wl16[3][FF * FF];        // W^T lo*2048 (fp16)

// ---------------- small helpers ---------------------------------------------
__device__ __forceinline__ int load_edge(const void* ei, long long idx) {
    if (g_is64) return (int)((const long long*)ei)[idx];
    return ((const int*)ei)[idx];
}

__global__ void k_detect_init(const int* p) {
    int i = blockIdx.x * blockDim.x + threadIdx.x;
    if (i < NN) { g_cnt[i] = 0; g_cursor[i] = 0; }
    if (blockIdx.x == 0 && threadIdx.x == 0) {
        int any = 0;
        #pragma unroll
        for (int j = 1; j < 64; j += 2) any |= p[j];
        g_is64 = (any == 0) ? 1 : 0;
    }
}

__global__ void k_count(const void* ei) {
    int e = blockIdx.x * blockDim.x + threadIdx.x;
    if (e >= EE) return;
    int dst = load_edge(ei, (long long)EE + e);
    atomicAdd(&g_cnt[dst], 1);
}

#define SCAN_PER 49
__global__ void k_scan() {
    __shared__ int warptot[32];
    int tid  = threadIdx.x;
    int lane = tid & 31;
    int wid  = tid >> 5;
    int base = tid * SCAN_PER;
    int sum = 0;
    #pragma unroll 7
    for (int i = 0; i < SCAN_PER; i++) {
        int idx = base + i;
        sum += (idx < NN) ? g_cnt[idx] : 0;
    }
    int x = sum;
    #pragma unroll
    for (int off = 1; off < 32; off <<= 1) {
        int n = __shfl_up_sync(0xffffffffu, x, off);
        if (lane >= off) x += n;
    }
    if (lane == 31) warptot[wid] = x;
    __syncthreads();
    if (wid == 0) {
        int w = warptot[lane];
        #pragma unroll
        for (int off = 1; off < 32; off <<= 1) {
            int n = __shfl_up_sync(0xffffffffu, w, off);
            if (lane >= off) w += n;
        }
        warptot[lane] = w;
    }
    __syncthreads();
    int offset = x - sum;
    if (wid > 0) offset += warptot[wid - 1];
    int running = offset;
    #pragma unroll 7
    for (int i = 0; i < SCAN_PER; i++) {
        int idx = base + i;
        if (idx < NN) {
            int c = g_cnt[idx];
            g_rowstart[idx] = running;
            g_dis[idx] = rsqrtf((float)(c + 1));  // +1 self-loop
            running += c;
        } else if (idx == NN) {
            g_rowstart[idx] = running;
        }
    }
}

__global__ void k_build(const void* ei) {
    int e = blockIdx.x * blockDim.x + threadIdx.x;
    if (e >= EE) return;
    int src = load_edge(ei, e);
    int dst = load_edge(ei, (long long)EE + e);
    float w = g_dis[src] * g_dis[dst];
    int pos = g_rowstart[dst] + atomicAdd(&g_cursor[dst], 1);
    g_esrc[pos]  = src;
    g_enorm[pos] = w;
}

// --- weight split/transpose: all 3 hidden layers -> f16 hi + f16 lo*2048 -----
__global__ void k_wsplit3(const float* __restrict__ W0,
                          const float* __restrict__ W1,
                          const float* __restrict__ W2,
                          __half* __restrict__ fhi,
                          __half* __restrict__ flo) {
    int layer = blockIdx.x >> 8;                     // 256 blocks per layer
    int i = (blockIdx.x & 255) * 256 + threadIdx.x;  // i = k*256 + n
    int k = i >> 8, n = i & 255;
    const float* W = (layer == 0) ? W0 : (layer == 1) ? W1 : W2;
    float w = W[i];
    __half h = __float2half_rn(w);
    __half l = __float2half_rn((w - __half2float(h)) * 2048.f);
    size_t off = (size_t)layer * FF * FF + n * 256 + k;
    fhi[off] = h;
    flo[off] = l;
}

// --- input quantization: x fp32 -> fp16 (8 elems/thread) ---------------------
__global__ void k_xcvt(const float* __restrict__ x, __half* __restrict__ X16) {
    size_t i = ((size_t)blockIdx.x * 256 + threadIdx.x) * 8;
    float4 f0 = *(const float4*)(x + i);
    float4 f1 = *(const float4*)(x + i + 4);
    uint4 v;
    *(__half2*)&v.x = __floats2half2_rn(f0.x, f0.y);
    *(__half2*)&v.y = __floats2half2_rn(f0.z, f0.w);
    *(__half2*)&v.z = __floats2half2_rn(f1.x, f1.y);
    *(__half2*)&v.w = __floats2half2_rn(f1.z, f1.w);
    *(uint4*)(X16 + i) = v;
}

// ---------------- GEMM constants ---------------------------------------------
#define AST 72    // A smem row stride (16-bit elems): +16B/row phase, LDSM clean
#define WST 264   // W smem row stride
#define SM_W   (128 * WST * 2)
#define SM_A   (128 * AST * 2)
#define SM_TOTH (2 * SM_W + SM_A)       // 153600 B

__device__ __forceinline__ void mma_f16(float c[4], const uint32_t a[4],
                                        const uint32_t b[2]) {
    asm volatile(
        "mma.sync.aligned.m16n8k16.row.col.f32.f16.f16.f32 "
        "{%0,%1,%2,%3}, {%4,%5,%6,%7}, {%8,%9}, {%0,%1,%2,%3};"
        : "+f"(c[0]), "+f"(c[1]), "+f"(c[2]), "+f"(c[3])
        : "r"(a[0]), "r"(a[1]), "r"(a[2]), "r"(a[3]), "r"(b[0]), "r"(b[1]));
}
#define LDSM4(r0, r1, r2, r3, addr) \
    asm volatile("ldmatrix.sync.aligned.m8n8.x4.shared.b16 {%0,%1,%2,%3}, [%4];" \
                 : "=r"(r0), "=r"(r1), "=r"(r2), "=r"(r3) : "r"(addr))

// -------- GEMM: fp16 A (exact), W split f16 x2, optional fused relu ----------
template <bool RELU>
__global__ __launch_bounds__(256, 1)
void k_gemm_h(const __half* __restrict__ A,
              const __half* __restrict__ WThi,
              const __half* __restrict__ WTlo,
              __half* __restrict__ C) {
    extern __shared__ __align__(16) char smem[];
    __half* sWhi = (__half*)smem;
    __half* sWlo = sWhi + 128 * WST;
    __half* sA   = sWlo + 128 * WST;

    const int tid  = threadIdx.x;
    const int wid  = tid >> 5;
    const int lane = tid & 31;
    const int warpM = wid & 1;
    const int warpN = wid >> 1;
    const int rowBase = blockIdx.x * 128;
    const int nGlob   = blockIdx.y * 128;

    {
        const __half* srcH = WThi + (size_t)nGlob * 256;
        const __half* srcL = WTlo + (size_t)nGlob * 256;
        #pragma unroll
        for (int it = 0; it < 16; it++) {
            int idx = tid + it * 256;
            int n  = idx >> 5;
            int kq = idx & 31;
            *(uint4*)(sWhi + n * WST + kq * 8) =
                *(const uint4*)(srcH + n * 256 + kq * 8);
            *(uint4*)(sWlo + n * WST + kq * 8) =
                *(const uint4*)(srcL + n * 256 + kq * 8);
        }
    }

    float acch[4][4][4], accl[4][4][4];
    #pragma unroll
    for (int i = 0; i < 4; i++)
        #pragma unroll
        for (int j = 0; j < 4; j++)
            #pragma unroll
            for (int q = 0; q < 4; q++) { acch[i][j][q] = 0.f; accl[i][j][q] = 0.f; }

    const uint32_t aBaseSm = (uint32_t)__cvta_generic_to_shared(sA) +
        (uint32_t)(((warpM * 64 + (lane & 15)) * AST + (lane >> 4) * 8) * 2);
    const uint32_t bHiBase = (uint32_t)__cvta_generic_to_shared(sWhi) +
        (uint32_t)(((warpN * 32 + ((lane >> 4) << 3) + (lane & 7)) * WST +
                    ((lane >> 3) & 1) * 8) * 2);
    const uint32_t bLoBase = bHiBase + (uint32_t)(128 * WST * 2);

    const int rS = tid >> 1;
    const int hS = tid & 1;
    const bool vS = (rowBase + rS) < NN;
    const __half* aBase = A + (size_t)(rowBase + rS) * 256 + hS * 32;
    const uint4 z4 = make_uint4(0, 0, 0, 0);

    uint4 pf[4];
    #pragma unroll
    for (int q = 0; q < 4; q++)
        pf[q] = vS ? *(const uint4*)((const char*)aBase + q * 16) : z4;

    const __half2 zh = __float2half2_rn(0.f);
    for (int kc = 0; kc < 4; kc++) {
        __syncthreads();
        {
            __half* dst = sA + rS * AST + hS * 32;
            #pragma unroll
            for (int q = 0; q < 4; q++) {
                uint4 v = pf[q];
                if (RELU) {
                    __half2* h2 = (__half2*)&v;
                    h2[0] = __hmax2(h2[0], zh);
                    h2[1] = __hmax2(h2[1], zh);
                    h2[2] = __hmax2(h2[2], zh);
                    h2[3] = __hmax2(h2[3], zh);
                }
                *(uint4*)(dst + q * 8) = v;
            }
        }
        __syncthreads();

        if (kc < 3) {
            const __half* nxt = aBase + (kc + 1) * 64;
            #pragma unroll
            for (int q = 0; q < 4; q++)
                pf[q] = vS ? *(const uint4*)((const char*)nxt + q * 16) : z4;
        }

        #pragma unroll
        for (int ks = 0; ks < 4; ks++) {
            const uint32_t aOff = (uint32_t)(ks * 32);
            const uint32_t bOff = (uint32_t)(kc * 128 + ks * 32);
            uint32_t ah[4][4], bh[4][2], bl[4][2];
            #pragma unroll
            for (int i = 0; i < 4; i++)
                LDSM4(ah[i][0], ah[i][1], ah[i][2], ah[i][3],
                      aBaseSm + (uint32_t)(i * 16 * AST * 2) + aOff);
            #pragma unroll
            for (int jj = 0; jj < 2; jj++) {
                LDSM4(bh[2 * jj][0], bh[2 * jj][1], bh[2 * jj + 1][0], bh[2 * jj + 1][1],
                      bHiBase + (uint32_t)(jj * 16 * WST * 2) + bOff);
                LDSM4(bl[2 * jj][0], bl[2 * jj][1], bl[2 * jj + 1][0], bl[2 * jj + 1][1],
                      bLoBase + (uint32_t)(jj * 16 * WST * 2) + bOff);
            }
            #pragma unroll
            for (int i = 0; i < 4; i++)
                #pragma unroll
                for (int j = 0; j < 4; j++) {
                    mma_f16(acch[i][j], ah[i], bh[j]);
                    mma_f16(accl[i][j], ah[i], bl[j]);
                }
        }
    }

    const float S = 1.f / 2048.f;
    const int g  = lane >> 2;
    const int cc = lane & 3;
    #pragma unroll
    for (int i = 0; i < 4; i++) {
        int row0 = rowBase + warpM * 64 + i * 16 + g;
        int row1 = row0 + 8;
        #pragma unroll
        for (int j = 0; j < 4; j++) {
            int col = nGlob + warpN * 32 + j * 8 + 2 * cc;
            if (row0 < NN)
                *(__half2*)(C + (size_t)row0 * 256 + col) = __floats2half2_rn(
                    fmaf(accl[i][j][0], S, acch[i][j][0]),
                    fmaf(accl[i][j][1], S, acch[i][j][1]));
            if (row1 < NN)
                *(__half2*)(C + (size_t)row1 * 256 + col) = __floats2half2_rn(
                    fmaf(accl[i][j][2], S, acch[i][j][2]),
                    fmaf(accl[i][j][3], S, acch[i][j][3]));
        }
    }
}

// ------- aggregation, fp16 msgs -> fp16 H (+bias, relu deferred) -------------
__global__ void k_agg_h(const uint4* __restrict__ Th4,
                        const float* __restrict__ bias,
                        __half* __restrict__ O) {
    int warp = (blockIdx.x * blockDim.x + threadIdx.x) >> 5;
    int lane = threadIdx.x & 31;
    if (warp >= NN) return;
    int node = warp;
    float ws = g_dis[node];
    ws *= ws;  // self-loop weight dis^2 = 1/deg

    float acc[8];
    {
        uint4 sv = Th4[(size_t)node * 32 + lane];
        float2 f0 = __half22float2(*(__half2*)&sv.x);
        float2 f1 = __half22float2(*(__half2*)&sv.y);
        float2 f2 = __half22float2(*(__half2*)&sv.z);
        float2 f3 = __half22float2(*(__half2*)&sv.w);
        acc[0] = f0.x * ws; acc[1] = f0.y * ws;
        acc[2] = f1.x * ws; acc[3] = f1.y * ws;
        acc[4] = f2.x * ws; acc[5] = f2.y * ws;
        acc[6] = f3.x * ws; acc[7] = f3.y * ws;
    }

    int p0 = g_rowstart[node];
    int p1 = g_rowstart[node + 1];
    for (int p = p0; p < p1; p++) {
        int   s = g_esrc[p];
        float w = g_enorm[p];
        uint4 v = Th4[(size_t)s * 32 + lane];
        float2 f0 = __half22float2(*(__half2*)&v.x);
        float2 f1 = __half22float2(*(__half2*)&v.y);
        float2 f2 = __half22float2(*(__half2*)&v.z);
        float2 f3 = __half22float2(*(__half2*)&v.w);
        acc[0] = fmaf(f0.x, w, acc[0]); acc[1] = fmaf(f0.y, w, acc[1]);
        acc[2] = fmaf(f1.x, w, acc[2]); acc[3] = fmaf(f1.y, w, acc[3]);
        acc[4] = fmaf(f2.x, w, acc[4]); acc[5] = fmaf(f2.y, w, acc[5]);
        acc[6] = fmaf(f3.x, w, acc[6]); acc[7] = fmaf(f3.y, w, acc[7]);
    }

    float4 b0 = ((const float4*)bias)[lane * 2];
    float4 b1 = ((const float4*)bias)[lane * 2 + 1];
    uint4 ov;
    *(__half2*)&ov.x = __floats2half2_rn(acc[0] + b0.x, acc[1] + b0.y);
    *(__half2*)&ov.y = __floats2half2_rn(acc[2] + b0.z, acc[3] + b0.w);
    *(__half2*)&ov.z = __floats2half2_rn(acc[4] + b1.x, acc[5] + b1.y);
    *(__half2*)&ov.w = __floats2half2_rn(acc[6] + b1.z, acc[7] + b1.w);
    *(uint4*)(O + (size_t)node * 256 + lane * 8) = ov;
}

// --- layer-3 aggregation FUSED with layer-4 GEMM: t2 = relu(agg+b2) @ W3 -----
__global__ void k_agg_last(const uint4* __restrict__ Th4,
                           const float* __restrict__ bias,
                           const float* __restrict__ W3,
                           float* __restrict__ t2) {
    int warp = (blockIdx.x * blockDim.x + threadIdx.x) >> 5;
    int lane = threadIdx.x & 31;
    if (warp >= NN) return;
    int node = warp;
    float ws = g_dis[node];
    ws *= ws;

    float acc[8];
    {
        uint4 sv = Th4[(size_t)node * 32 + lane];
        float2 f0 = __half22float2(*(__half2*)&sv.x);
        float2 f1 = __half22float2(*(__half2*)&sv.y);
        float2 f2 = __half22float2(*(__half2*)&sv.z);
        float2 f3 = __half22float2(*(__half2*)&sv.w);
        acc[0] = f0.x * ws; acc[1] = f0.y * ws;
        acc[2] = f1.x * ws; acc[3] = f1.y * ws;
        acc[4] = f2.x * ws; acc[5] = f2.y * ws;
        acc[6] = f3.x * ws; acc[7] = f3.y * ws;
    }

    int p0 = g_rowstart[node];
    int p1 = g_rowstart[node + 1];
    for (int p = p0; p < p1; p++) {
        int   s = g_esrc[p];
        float w = g_enorm[p];
        uint4 v = Th4[(size_t)s * 32 + lane];
        float2 f0 = __half22float2(*(__half2*)&v.x);
        float2 f1 = __half22float2(*(__half2*)&v.y);
        float2 f2 = __half22float2(*(__half2*)&v.z);
        float2 f3 = __half22float2(*(__half2*)&v.w);
        acc[0] = fmaf(f0.x, w, acc[0]); acc[1] = fmaf(f0.y, w, acc[1]);
        acc[2] = fmaf(f1.x, w, acc[2]); acc[3] = fmaf(f1.y, w, acc[3]);
        acc[4] = fmaf(f2.x, w, acc[4]); acc[5] = fmaf(f2.y, w, acc[5]);
        acc[6] = fmaf(f3.x, w, acc[6]); acc[7] = fmaf(f3.y, w, acc[7]);
    }

    float4 b0 = ((const float4*)bias)[lane * 2];
    float4 b1 = ((const float4*)bias)[lane * 2 + 1];
    float h[8] = {acc[0] + b0.x, acc[1] + b0.y, acc[2] + b0.z, acc[3] + b0.w,
                  acc[4] + b1.x, acc[5] + b1.y, acc[6] + b1.z, acc[7] + b1.w};
    float s0 = 0.f, s1 = 0.f;
    #pragma unroll
    for (int q = 0; q < 8; q++) {
        float hv = fmaxf(h[q], 0.f);
        float2 w = ((const float2*)W3)[lane * 8 + q];
        s0 = fmaf(hv, w.x, s0);
        s1 = fmaf(hv, w.y, s1);
    }
    #pragma unroll
    for (int off = 16; off; off >>= 1) {
        s0 += __shfl_xor_sync(0xffffffffu, s0, off);
        s1 += __shfl_xor_sync(0xffffffffu, s1, off);
    }
    if (lane == 0) { t2[node * 2] = s0; t2[node * 2 + 1] = s1; }
}

// ---------------- final aggregation (F=2) into d_out -------------------------
__global__ void k_agg2(const float* __restrict__ t2,
                       const float* __restrict__ b3,
                       float* __restrict__ out) {
    int warp = (blockIdx.x * blockDim.x + threadIdx.x) >> 5;
    int lane = threadIdx.x & 31;
    if (warp >= NN) return;
    int node = warp;
    int p0 = g_rowstart[node];
    int p1 = g_rowstart[node + 1];
    float s0 = 0.f, s1 = 0.f;
    for (int p = p0 + lane; p < p1; p += 32) {
        int   s = g_esrc[p];
        float w = g_enorm[p];
        s0 = fmaf(t2[s * 2],     w, s0);
        s1 = fmaf(t2[s * 2 + 1], w, s1);
    }
    #pragma unroll
    for (int off = 16; off; off >>= 1) {
        s0 += __shfl_xor_sync(0xffffffffu, s0, off);
        s1 += __shfl_xor_sync(0xffffffffu, s1, off);
    }
    if (lane == 0) {
        float ws = g_dis[node];
        ws *= ws;
        out[node * 2]     = s0 + t2[node * 2]     * ws + b3[0];
        out[node * 2 + 1] = s1 + t2[node * 2 + 1] * ws + b3[1];
    }
}

// ---------------- launch ------------------------------------------------------
extern "C" void kernel_launch(void* const* d_in, const int* in_sizes, int n_in,
                              void* d_out, int out_size) {
    const float* x  = (const float*)d_in[0];
    const void*  ei = d_in[1];
    const float* W0 = (const float*)d_in[2];
    const float* b0 = (const float*)d_in[3];
    const float* W1 = (const float*)d_in[4];
    const float* b1 = (const float*)d_in[5];
    const float* W2 = (const float*)d_in[6];
    const float* b2 = (const float*)d_in[7];
    const float* W3 = (const float*)d_in[8];
    const float* b3 = (const float*)d_in[9];
    float* out = (float*)d_out;

    float* t2;
    __half *X16, *Th, *HA, *HB, *Wh16, *Wl16;
    cudaGetSymbolAddress((void**)&X16,  g_X16);
    cudaGetSymbolAddress((void**)&Th,   g_Th);
    cudaGetSymbolAddress((void**)&HA,   g_HA);
    cudaGetSymbolAddress((void**)&HB,   g_HB);
    cudaGetSymbolAddress((void**)&t2,   g_t2);
    cudaGetSymbolAddress((void**)&Wh16, g_Wh16);
    cudaGetSymbolAddress((void**)&Wl16, g_Wl16);

    static int smem_set = 0;
    if (!smem_set) {
        cudaFuncSetAttribute(k_gemm_h<false>,
                             cudaFuncAttributeMaxDynamicSharedMemorySize, SM_TOTH);
        cudaFuncSetAttribute(k_gemm_h<true>,
                             cudaFuncAttributeMaxDynamicSharedMemorySize, SM_TOTH);
        smem_set = 1;
    }

    const int nodeBlocks = (NN + 255) / 256;
    const int edgeBlocks = (EE + 255) / 256;
    const int warpBlocks = (NN + 7) / 8;
    dim3 gemmGrid(NTILES, 2);

    // ---- graph preprocessing ----
    k_detect_init<<<nodeBlocks, 256>>>((const int*)ei);
    k_count<<<edgeBlocks, 256>>>(ei);
    k_scan<<<1, 1024>>>();
    k_build<<<edgeBlocks, 256>>>(ei);

    // ---- weight split + input quantization ----
    k_wsplit3<<<768, 256>>>(W0, W1, W2, Wh16, Wl16);
    k_xcvt<<<6250, 256>>>(x, X16);

    // ---- layer 1 (fp16 A exact, no relu) ----
    k_gemm_h<false><<<gemmGrid, 256, SM_TOTH>>>(X16, Wh16, Wl16, Th);
    k_agg_h<<<warpBlocks, 256>>>((const uint4*)Th, b0, HA);
    // ---- layer 2 ----
    k_gemm_h<true><<<gemmGrid, 256, SM_TOTH>>>(HA, Wh16 + FF * FF, Wl16 + FF * FF, Th);
    k_agg_h<<<warpBlocks, 256>>>((const uint4*)Th, b1, HB);
    // ---- layer 3 + fused layer-4 GEMM ----
    k_gemm_h<true><<<gemmGrid, 256, SM_TOTH>>>(HB, Wh16 + 2 * FF * FF, Wl16 + 2 * FF * FF, Th);
    k_agg_last<<<warpBlocks, 256>>>((const uint4*)Th, b2, W3, t2);
    // ---- final edge aggregation ----
    k_agg2<<<warpBlocks, 256>>>(t2, b3, out);
}

// round 17
// speedup vs baseline: 1.6417x; 1.1142x over previous
#include <cuda_runtime.h>
#include <cuda_fp16.h>
#include <math.h>
#include <stdint.h>

#define NN 50000
#define EE 800000
#define FF 256
#define NTILES 391  // ceil(50000/128)

// ---------------- device scratch (no runtime allocation allowed) ------------
__device__ int   g_is64;
__device__ int   g_cnt[NN];
__device__ int   g_cursor[NN];
__device__ int   g_rowstart[NN + 1];
__device__ float g_dis[NN];
__device__ int   g_esrc[EE];
__device__ float g_enorm[EE];
__device__ __half g_X16[(size_t)NN * FF];    // fp16-quantized input x
__device__ __half g_Th[(size_t)NN * FF];     // GEMM output messages (fp16)
__device__ __half g_HA[(size_t)NN * FF];     // hidden activations (fp16)
__device__ __half g_HB[(size_t)NN * FF];
__device__ float g_t2[NN * 2];
__device__ __half g_W16[3][FF * FF];         // W^T fp16, layers 0-2

// ---------------- small helpers ---------------------------------------------
// low 32-bit word of edge index (values < 2^31, so exact for int64 too)
__device__ __forceinline__ int load_edge32(const int* ei, long long idx) {
    return g_is64 ? ei[2 * idx] : ei[idx];
}

__global__ void k_detect_init(const int* p) {
    int i = blockIdx.x * blockDim.x + threadIdx.x;
    if (i < NN) { g_cnt[i] = 0; g_cursor[i] = 0; }
    if (blockIdx.x == 0 && threadIdx.x == 0) {
        int any = 0;
        #pragma unroll
        for (int j = 1; j < 64; j += 2) any |= p[j];
        g_is64 = (any == 0) ? 1 : 0;
    }
}

__global__ void k_count(const int* ei) {
    int e = blockIdx.x * blockDim.x + threadIdx.x;
    if (e >= EE) return;
    int dst = load_edge32(ei, (long long)EE + e);
    atomicAdd(&g_cnt[dst], 1);
}

#define SCAN_PER 49
__global__ void k_scan() {
    __shared__ int warptot[32];
    int tid  = threadIdx.x;
    int lane = tid & 31;
    int wid  = tid >> 5;
    int base = tid * SCAN_PER;
    int sum = 0;
    #pragma unroll 7
    for (int i = 0; i < SCAN_PER; i++) {
        int idx = base + i;
        sum += (idx < NN) ? g_cnt[idx] : 0;
    }
    int x = sum;
    #pragma unroll
    for (int off = 1; off < 32; off <<= 1) {
        int n = __shfl_up_sync(0xffffffffu, x, off);
        if (lane >= off) x += n;
    }
    if (lane == 31) warptot[wid] = x;
    __syncthreads();
    if (wid == 0) {
        int w = warptot[lane];
        #pragma unroll
        for (int off = 1; off < 32; off <<= 1) {
            int n = __shfl_up_sync(0xffffffffu, w, off);
            if (lane >= off) w += n;
        }
        warptot[lane] = w;
    }
    __syncthreads();
    int offset = x - sum;
    if (wid > 0) offset += warptot[wid - 1];
    int running = offset;
    #pragma unroll 7
    for (int i = 0; i < SCAN_PER; i++) {
        int idx = base + i;
        if (idx < NN) {
            int c = g_cnt[idx];
            g_rowstart[idx] = running;
            g_dis[idx] = rsqrtf((float)(c + 1));  // +1 self-loop
            running += c;
        } else if (idx == NN) {
            g_rowstart[idx] = running;
        }
    }
}

__global__ void k_build(const int* ei) {
    int e = blockIdx.x * blockDim.x + threadIdx.x;
    if (e >= EE) return;
    int src = load_edge32(ei, e);
    int dst = load_edge32(ei, (long long)EE + e);
    float w = g_dis[src] * g_dis[dst];
    int pos = g_rowstart[dst] + atomicAdd(&g_cursor[dst], 1);
    g_esrc[pos]  = src;
    g_enorm[pos] = w;
}

// --- weight transpose+quantize: all 3 hidden layers -> fp16 ------------------
__global__ void k_wcvt3(const float* __restrict__ W0,
                        const float* __restrict__ W1,
                        const float* __restrict__ W2,
                        __half* __restrict__ f16) {
    int layer = blockIdx.x >> 8;                     // 256 blocks per layer
    int i = (blockIdx.x & 255) * 256 + threadIdx.x;  // i = k*256 + n
    int k = i >> 8, n = i & 255;
    const float* W = (layer == 0) ? W0 : (layer == 1) ? W1 : W2;
    f16[(size_t)layer * FF * FF + n * 256 + k] = __float2half_rn(W[i]);
}

// --- input quantization: x fp32 -> fp16 (8 elems/thread) ---------------------
__global__ void k_xcvt(const float* __restrict__ x, __half* __restrict__ X16) {
    size_t i = ((size_t)blockIdx.x * 256 + threadIdx.x) * 8;
    float4 f0 = *(const float4*)(x + i);
    float4 f1 = *(const float4*)(x + i + 4);
    uint4 v;
    *(__half2*)&v.x = __floats2half2_rn(f0.x, f0.y);
    *(__half2*)&v.y = __floats2half2_rn(f0.z, f0.w);
    *(__half2*)&v.z = __floats2half2_rn(f1.x, f1.y);
    *(__half2*)&v.w = __floats2half2_rn(f1.z, f1.w);
    *(uint4*)(X16 + i) = v;
}

// ---------------- GEMM constants ---------------------------------------------
#define AST 72    // A smem row stride (16-bit elems): +16B/row phase, LDSM clean
#define WST 264   // W smem row stride
#define SM_W   (128 * WST * 2)
#define SM_A   (128 * AST * 2)
#define SM_TOT1 (SM_W + SM_A)           // 86016 B -> 2 CTAs/SM

__device__ __forceinline__ void mma_f16(float c[4], const uint32_t a[4],
                                        const uint32_t b[2]) {
    asm volatile(
        "mma.sync.aligned.m16n8k16.row.col.f32.f16.f16.f32 "
        "{%0,%1,%2,%3}, {%4,%5,%6,%7}, {%8,%9}, {%0,%1,%2,%3};"
        : "+f"(c[0]), "+f"(c[1]), "+f"(c[2]), "+f"(c[3])
        : "r"(a[0]), "r"(a[1]), "r"(a[2]), "r"(a[3]), "r"(b[0]), "r"(b[1]));
}
#define LDSM4(r0, r1, r2, r3, addr) \
    asm volatile("ldmatrix.sync.aligned.m8n8.x4.shared.b16 {%0,%1,%2,%3}, [%4];" \
                 : "=r"(r0), "=r"(r1), "=r"(r2), "=r"(r3) : "r"(addr))

// -------- GEMM: fp16 A (exact), single fp16 W, optional fused relu -----------
template <bool RELU>
__global__ __launch_bounds__(256, 2)
void k_gemm_h(const __half* __restrict__ A,
              const __half* __restrict__ WT,
              __half* __restrict__ C) {
    extern __shared__ __align__(16) char smem[];
    __half* sW = (__half*)smem;
    __half* sA = sW + 128 * WST;

    const int tid  = threadIdx.x;
    const int wid  = tid >> 5;
    const int lane = tid & 31;
    const int warpM = wid & 1;
    const int warpN = wid >> 1;
    const int rowBase = blockIdx.x * 128;
    const int nGlob   = blockIdx.y * 128;

    {
        const __half* src = WT + (size_t)nGlob * 256;
        #pragma unroll
        for (int it = 0; it < 16; it++) {
            int idx = tid + it * 256;
            int n  = idx >> 5;
            int kq = idx & 31;
            *(uint4*)(sW + n * WST + kq * 8) =
                *(const uint4*)(src + n * 256 + kq * 8);
        }
    }

    float acc[4][4][4];
    #pragma unroll
    for (int i = 0; i < 4; i++)
        #pragma unroll
        for (int j = 0; j < 4; j++)
            #pragma unroll
            for (int q = 0; q < 4; q++) acc[i][j][q] = 0.f;

    const uint32_t aBaseSm = (uint32_t)__cvta_generic_to_shared(sA) +
        (uint32_t)(((warpM * 64 + (lane & 15)) * AST + (lane >> 4) * 8) * 2);
    const uint32_t bBase = (uint32_t)__cvta_generic_to_shared(sW) +
        (uint32_t)(((warpN * 32 + ((lane >> 4) << 3) + (lane & 7)) * WST +
                    ((lane >> 3) & 1) * 8) * 2);

    const int rS = tid >> 1;
    const int hS = tid & 1;
    const bool vS = (rowBase + rS) < NN;
    const __half* aBase = A + (size_t)(rowBase + rS) * 256 + hS * 32;
    const uint4 z4 = make_uint4(0, 0, 0, 0);

    uint4 pf[4];
    #pragma unroll
    for (int q = 0; q < 4; q++)
        pf[q] = vS ? *(const uint4*)((const char*)aBase + q * 16) : z4;

    const __half2 zh = __float2half2_rn(0.f);
    for (int kc = 0; kc < 4; kc++) {
        __syncthreads();
        {
            __half* dst = sA + rS * AST + hS * 32;
            #pragma unroll
            for (int q = 0; q < 4; q++) {
                uint4 v = pf[q];
                if (RELU) {
                    __half2* h2 = (__half2*)&v;
                    h2[0] = __hmax2(h2[0], zh);
                    h2[1] = __hmax2(h2[1], zh);
                    h2[2] = __hmax2(h2[2], zh);
                    h2[3] = __hmax2(h2[3], zh);
                }
                *(uint4*)(dst + q * 8) = v;
            }
        }
        __syncthreads();

        if (kc < 3) {
            const __half* nxt = aBase + (kc + 1) * 64;
            #pragma unroll
            for (int q = 0; q < 4; q++)
                pf[q] = vS ? *(const uint4*)((const char*)nxt + q * 16) : z4;
        }

        #pragma unroll
        for (int ks = 0; ks < 4; ks++) {
            const uint32_t aOff = (uint32_t)(ks * 32);
            const uint32_t bOff = (uint32_t)(kc * 128 + ks * 32);
            uint32_t ah[4][4], bb[4][2];
            #pragma unroll
            for (int i = 0; i < 4; i++)
                LDSM4(ah[i][0], ah[i][1], ah[i][2], ah[i][3],
                      aBaseSm + (uint32_t)(i * 16 * AST * 2) + aOff);
            #pragma unroll
            for (int jj = 0; jj < 2; jj++)
                LDSM4(bb[2 * jj][0], bb[2 * jj][1], bb[2 * jj + 1][0], bb[2 * jj + 1][1],
                      bBase + (uint32_t)(jj * 16 * WST * 2) + bOff);
            #pragma unroll
            for (int i = 0; i < 4; i++)
                #pragma unroll
                for (int j = 0; j < 4; j++)
                    mma_f16(acc[i][j], ah[i], bb[j]);
        }
    }

    const int g  = lane >> 2;
    const int cc = lane & 3;
    #pragma unroll
    for (int i = 0; i < 4; i++) {
        int row0 = rowBase + warpM * 64 + i * 16 + g;
        int row1 = row0 + 8;
        #pragma unroll
        for (int j = 0; j < 4; j++) {
            int col = nGlob + warpN * 32 + j * 8 + 2 * cc;
            if (row0 < NN)
                *(__half2*)(C + (size_t)row0 * 256 + col) =
                    __floats2half2_rn(acc[i][j][0], acc[i][j][1]);
            if (row1 < NN)
                *(__half2*)(C + (size_t)row1 * 256 + col) =
                    __floats2half2_rn(acc[i][j][2], acc[i][j][3]);
        }
    }
}

// ------- aggregation, fp16 msgs -> fp16 H (+bias, relu deferred) -------------
__global__ void k_agg_h(const uint4* __restrict__ Th4,
                        const float* __restrict__ bias,
                        __half* __restrict__ O) {
    int warp = (blockIdx.x * blockDim.x + threadIdx.x) >> 5;
    int lane = threadIdx.x & 31;
    if (warp >= NN) return;
    int node = warp;
    float ws = g_dis[node];
    ws *= ws;  // self-loop weight dis^2 = 1/deg

    float acc[8];
    {
        uint4 sv = Th4[(size_t)node * 32 + lane];
        float2 f0 = __half22float2(*(__half2*)&sv.x);
        float2 f1 = __half22float2(*(__half2*)&sv.y);
        float2 f2 = __half22float2(*(__half2*)&sv.z);
        float2 f3 = __half22float2(*(__half2*)&sv.w);
        acc[0] = f0.x * ws; acc[1] = f0.y * ws;
        acc[2] = f1.x * ws; acc[3] = f1.y * ws;
        acc[4] = f2.x * ws; acc[5] = f2.y * ws;
        acc[6] = f3.x * ws; acc[7] = f3.y * ws;
    }

    int p0 = g_rowstart[node];
    int p1 = g_rowstart[node + 1];
    for (int p = p0; p < p1; p++) {
        int   s = g_esrc[p];
        float w = g_enorm[p];
        uint4 v = Th4[(size_t)s * 32 + lane];
        float2 f0 = __half22float2(*(__half2*)&v.x);
        float2 f1 = __half22float2(*(__half2*)&v.y);
        float2 f2 = __half22float2(*(__half2*)&v.z);
        float2 f3 = __half22float2(*(__half2*)&v.w);
        acc[0] = fmaf(f0.x, w, acc[0]); acc[1] = fmaf(f0.y, w, acc[1]);
        acc[2] = fmaf(f1.x, w, acc[2]); acc[3] = fmaf(f1.y, w, acc[3]);
        acc[4] = fmaf(f2.x, w, acc[4]); acc[5] = fmaf(f2.y, w, acc[5]);
        acc[6] = fmaf(f3.x, w, acc[6]); acc[7] = fmaf(f3.y, w, acc[7]);
    }

    float4 b0 = ((const float4*)bias)[lane * 2];
    float4 b1 = ((const float4*)bias)[lane * 2 + 1];
    uint4 ov;
    *(__half2*)&ov.x = __floats2half2_rn(acc[0] + b0.x, acc[1] + b0.y);
    *(__half2*)&ov.y = __floats2half2_rn(acc[2] + b0.z, acc[3] + b0.w);
    *(__half2*)&ov.z = __floats2half2_rn(acc[4] + b1.x, acc[5] + b1.y);
    *(__half2*)&ov.w = __floats2half2_rn(acc[6] + b1.z, acc[7] + b1.w);
    *(uint4*)(O + (size_t)node * 256 + lane * 8) = ov;
}

// --- layer-3 aggregation FUSED with layer-4 GEMM: t2 = relu(agg+b2) @ W3 -----
__global__ void k_agg_last(const uint4* __restrict__ Th4,
                           const float* __restrict__ bias,
                           const float* __restrict__ W3,
                           float* __restrict__ t2) {
    int warp = (blockIdx.x * blockDim.x + threadIdx.x) >> 5;
    int lane = threadIdx.x & 31;
    if (warp >= NN) return;
    int node = warp;
    float ws = g_dis[node];
    ws *= ws;

    float acc[8];
    {
        uint4 sv = Th4[(size_t)node * 32 + lane];
        float2 f0 = __half22float2(*(__half2*)&sv.x);
        float2 f1 = __half22float2(*(__half2*)&sv.y);
        float2 f2 = __half22float2(*(__half2*)&sv.z);
        float2 f3 = __half22float2(*(__half2*)&sv.w);
        acc[0] = f0.x * ws; acc[1] = f0.y * ws;
        acc[2] = f1.x * ws; acc[3] = f1.y * ws;
        acc[4] = f2.x * ws; acc[5] = f2.y * ws;
        acc[6] = f3.x * ws; acc[7] = f3.y * ws;
    }

    int p0 = g_rowstart[node];
    int p1 = g_rowstart[node + 1];
    for (int p = p0; p < p1; p++) {
        int   s = g_esrc[p];
        float w = g_enorm[p];
        uint4 v = Th4[(size_t)s * 32 + lane];
        float2 f0 = __half22float2(*(__half2*)&v.x);
        float2 f1 = __half22float2(*(__half2*)&v.y);
        float2 f2 = __half22float2(*(__half2*)&v.z);
        float2 f3 = __half22float2(*(__half2*)&v.w);
        acc[0] = fmaf(f0.x, w, acc[0]); acc[1] = fmaf(f0.y, w, acc[1]);
        acc[2] = fmaf(f1.x, w, acc[2]); acc[3] = fmaf(f1.y, w, acc[3]);
        acc[4] = fmaf(f2.x, w, acc[4]); acc[5] = fmaf(f2.y, w, acc[5]);
        acc[6] = fmaf(f3.x, w, acc[6]); acc[7] = fmaf(f3.y, w, acc[7]);
    }

    float4 b0 = ((const float4*)bias)[lane * 2];
    float4 b1 = ((const float4*)bias)[lane * 2 + 1];
    float h[8] = {acc[0] + b0.x, acc[1] + b0.y, acc[2] + b0.z, acc[3] + b0.w,
                  acc[4] + b1.x, acc[5] + b1.y, acc[6] + b1.z, acc[7] + b1.w};
    float s0 = 0.f, s1 = 0.f;
    #pragma unroll
    for (int q = 0; q < 8; q++) {
        float hv = fmaxf(h[q], 0.f);
        float2 w = ((const float2*)W3)[lane * 8 + q];
        s0 = fmaf(hv, w.x, s0);
        s1 = fmaf(hv, w.y, s1);
    }
    #pragma unroll
    for (int off = 16; off; off >>= 1) {
        s0 += __shfl_xor_sync(0xffffffffu, s0, off);
        s1 += __shfl_xor_sync(0xffffffffu, s1, off);
    }
    if (lane == 0) { t2[node * 2] = s0; t2[node * 2 + 1] = s1; }
}

// ---------------- final aggregation (F=2) into d_out -------------------------
__global__ void k_agg2(const float* __restrict__ t2,
                       const float* __restrict__ b3,
                       float* __restrict__ out) {
    int warp = (blockIdx.x * blockDim.x + threadIdx.x) >> 5;
    int lane = threadIdx.x & 31;
    if (warp >= NN) return;
    int node = warp;
    int p0 = g_rowstart[node];
    int p1 = g_rowstart[node + 1];
    float s0 = 0.f, s1 = 0.f;
    for (int p = p0 + lane; p < p1; p += 32) {
        int   s = g_esrc[p];
        float w = g_enorm[p];
        s0 = fmaf(t2[s * 2],     w, s0);
        s1 = fmaf(t2[s * 2 + 1], w, s1);
    }
    #pragma unroll
    for (int off = 16; off; off >>= 1) {
        s0 += __shfl_xor_sync(0xffffffffu, s0, off);
        s1 += __shfl_xor_sync(0xffffffffu, s1, off);
    }
    if (lane == 0) {
        float ws = g_dis[node];
        ws *= ws;
        out[node * 2]     = s0 + t2[node * 2]     * ws + b3[0];
        out[node * 2 + 1] = s1 + t2[node * 2 + 1] * ws + b3[1];
    }
}

// ---------------- launch ------------------------------------------------------
extern "C" void kernel_launch(void* const* d_in, const int* in_sizes, int n_in,
                              void* d_out, int out_size) {
    const float* x  = (const float*)d_in[0];
    const int*   ei = (const int*)d_in[1];
    const float* W0 = (const float*)d_in[2];
    const float* b0 = (const float*)d_in[3];
    const float* W1 = (const float*)d_in[4];
    const float* b1 = (const float*)d_in[5];
    const float* W2 = (const float*)d_in[6];
    const float* b2 = (const float*)d_in[7];
    const float* W3 = (const float*)d_in[8];
    const float* b3 = (const float*)d_in[9];
    float* out = (float*)d_out;

    float* t2;
    __half *X16, *Th, *HA, *HB, *W16;
    cudaGetSymbolAddress((void**)&X16, g_X16);
    cudaGetSymbolAddress((void**)&Th,  g_Th);
    cudaGetSymbolAddress((void**)&HA,  g_HA);
    cudaGetSymbolAddress((void**)&HB,  g_HB);
    cudaGetSymbolAddress((void**)&t2,  g_t2);
    cudaGetSymbolAddress((void**)&W16, g_W16);

    static int smem_set = 0;
    if (!smem_set) {
        cudaFuncSetAttribute(k_gemm_h<false>,
                             cudaFuncAttributeMaxDynamicSharedMemorySize, SM_TOT1);
        cudaFuncSetAttribute(k_gemm_h<true>,
                             cudaFuncAttributeMaxDynamicSharedMemorySize, SM_TOT1);
        smem_set = 1;
    }

    const int nodeBlocks = (NN + 255) / 256;
    const int edgeBlocks = (EE + 255) / 256;
    const int warpBlocks = (NN + 7) / 8;
    dim3 gemmGrid(NTILES, 2);

    // ---- graph preprocessing ----
    k_detect_init<<<nodeBlocks, 256>>>(ei);
    k_count<<<edgeBlocks, 256>>>(ei);
    k_scan<<<1, 1024>>>();
    k_build<<<edgeBlocks, 256>>>(ei);

    // ---- weight transpose + input quantization ----
    k_wcvt3<<<768, 256>>>(W0, W1, W2, W16);
    k_xcvt<<<6250, 256>>>(x, X16);

    // ---- layer 1 (fp16 A exact, no relu) ----
    k_gemm_h<false><<<gemmGrid, 256, SM_TOT1>>>(X16, W16, Th);
    k_agg_h<<<warpBlocks, 256>>>((const uint4*)Th, b0, HA);
    // ---- layer 2 ----
    k_gemm_h<true><<<gemmGrid, 256, SM_TOT1>>>(HA, W16 + FF * FF, Th);
    k_agg_h<<<warpBlocks, 256>>>((const uint4*)Th, b1, HB);
    // ---- layer 3 + fused layer-4 GEMM ----
    k_gemm_h<true><<<gemmGrid, 256, SM_TOT1>>>(HB, W16 + 2 * FF * FF, Th);
    k_agg_last<<<warpBlocks, 256>>>((const uint4*)Th, b2, W3, t2);
    // ---- final edge aggregation ----
    k_agg2<<<warpBlocks, 256>>>(t2, b3, out);
}